// round 4
// baseline (speedup 1.0000x reference)
#include <cuda_runtime.h>
#include <math.h>

// ---------------- static problem config ----------------
#define BNN   8192      // total nodes (8*1024)
#define CC    64        // channels
#define KSEL  11        // K+1 neighbors
#define NLOC  1568      // 8 * 196 local hyperedges
#define NROWS 1024      // nodes per sample (32*32)

// ---------------- device scratch ----------------
__device__ float g_dists[(size_t)BNN * BNN];
__device__ float g_u[BNN * CC];
__device__ float g_sq[BNN];
__device__ int   g_inds[BNN * KSEL];
__device__ int   g_de[BNN];
__device__ float g_sknn[BNN * CC];
__device__ float g_sloc[NLOC * CC];
__device__ float g_z[BNN * CC];
__device__ float g_stats[2 * CC];

// ---------------- helpers ----------------
__device__ __forceinline__ int covdim(int r) {
    int lo = r - 4; if (lo < 0) lo = 0;
    int hi = r;     if (hi > 26) hi = 26;
    if (hi < lo) return 0;
    return hi / 2 - (lo + 1) / 2 + 1;
}

__device__ __forceinline__ float dv2f(int node) {
    int ln = node & (NROWS - 1);
    int r = ln >> 5, c = ln & 31;
    int deg = covdim(r) * covdim(c);
    return 1.0f / sqrtf((float)(KSEL + deg));
}

// float -> order-preserving uint
__device__ __forceinline__ unsigned ordkey(float f) {
    unsigned u = __float_as_uint(f);
    return (u & 0x80000000u) ? ~u : (u | 0x80000000u);
}
// inverse
__device__ __forceinline__ float invordkey(unsigned k) {
    unsigned u = (k & 0x80000000u) ? (k ^ 0x80000000u) : ~k;
    return __uint_as_float(u);
}

// sentinel: value=+INF, index=0xFFFFFFFF
#define KSENT 0xFF800000FFFFFFFFull

// ---------------- kZero ----------------
__global__ void kZero() {
    int i = blockIdx.x * 256 + threadIdx.x;
    if (i < BNN * CC) g_sknn[i] = 0.0f;
    if (i < BNN)      g_de[i]   = 0;
    if (i < 2 * CC)   g_stats[i] = 0.0f;
}

// ---------------- kA: sq norms + u = dv2 * (x W^T + b) ----------------
__global__ __launch_bounds__(256) void kA(const float* __restrict__ x,
                                          const float* __restrict__ W,
                                          const float* __restrict__ bconv) {
    __shared__ float Ws[CC][CC + 1];
    __shared__ float xs[4][CC];
    __shared__ float red[256];
    int tid = threadIdx.x;
    int node0 = blockIdx.x * 4;

    for (int i = tid; i < CC * CC; i += 256) Ws[i >> 6][i & 63] = W[i];
    for (int i = tid; i < 4 * CC; i += 256) xs[i >> 6][i & 63] = x[node0 * CC + i];
    __syncthreads();

    int n = tid >> 6, c = tid & 63;
    int node = node0 + n;

    float v = xs[n][c];
    red[tid] = v * v;
    __syncthreads();
    if (c < 32) red[tid] += red[tid + 32]; __syncthreads();
    if (c < 16) red[tid] += red[tid + 16]; __syncthreads();
    if (c < 8)  red[tid] += red[tid + 8];  __syncthreads();
    if (c < 4)  red[tid] += red[tid + 4];  __syncthreads();
    if (c < 2)  red[tid] += red[tid + 2];  __syncthreads();
    if (c < 1)  red[tid] += red[tid + 1];  __syncthreads();
    if (c == 0) g_sq[node] = red[tid];

    float acc = bconv[c];
#pragma unroll
    for (int k = 0; k < CC; k++) acc += xs[n][k] * Ws[c][k];
    g_u[node * CC + c] = acc * dv2f(node);
}

// ---------------- kB: fp32 distance GEMM ----------------
__global__ __launch_bounds__(256, 2) void kB(const float* __restrict__ x) {
    extern __shared__ float sm[];
    float (*As)[129] = (float (*)[129])sm;
    float (*Bs)[129] = (float (*)[129])(sm + 64 * 129);

    int ib = blockIdx.y, jb = blockIdx.x;
    int tid = threadIdx.x;

#pragma unroll
    for (int it = 0; it < 8; it++) {
        int idx = tid + it * 256;
        int r   = idx >> 4;
        int k4  = (idx & 15) * 4;
        float4 va = *(const float4*)(x + (size_t)(ib * 128 + r) * CC + k4);
        As[k4 + 0][r] = va.x; As[k4 + 1][r] = va.y;
        As[k4 + 2][r] = va.z; As[k4 + 3][r] = va.w;
        float4 vb = *(const float4*)(x + (size_t)(jb * 128 + r) * CC + k4);
        Bs[k4 + 0][r] = vb.x; Bs[k4 + 1][r] = vb.y;
        Bs[k4 + 2][r] = vb.z; Bs[k4 + 3][r] = vb.w;
    }
    __syncthreads();

    int tx = tid & 31;
    int ty = tid >> 5;

    float acc[16][4];
#pragma unroll
    for (int i = 0; i < 16; i++)
#pragma unroll
        for (int j = 0; j < 4; j++) acc[i][j] = 0.0f;

#pragma unroll 4
    for (int k = 0; k < 64; k++) {
        float a[16], b[4];
#pragma unroll
        for (int i = 0; i < 16; i++) a[i] = As[k][ty * 16 + i];
#pragma unroll
        for (int j = 0; j < 4; j++)  b[j] = Bs[k][tx + 32 * j];
#pragma unroll
        for (int i = 0; i < 16; i++)
#pragma unroll
            for (int j = 0; j < 4; j++) acc[i][j] += a[i] * b[j];
    }

    float sqi[16], sqj[4];
#pragma unroll
    for (int i = 0; i < 16; i++) sqi[i] = g_sq[ib * 128 + ty * 16 + i];
#pragma unroll
    for (int j = 0; j < 4; j++)  sqj[j] = g_sq[jb * 128 + tx + 32 * j];

#pragma unroll
    for (int i = 0; i < 16; i++) {
        size_t rowoff = (size_t)(ib * 128 + ty * 16 + i) * BNN;
#pragma unroll
        for (int j = 0; j < 4; j++) {
            int col = jb * 128 + tx + 32 * j;
            g_dists[rowoff + col] = sqi[i] + sqj[j] - 2.0f * acc[i][j];
        }
    }
}

// ---------------- kC: warp-per-row top-11, fp32 guard + replace-worst ----------------
__global__ __launch_bounds__(256) void kC() {
    int row  = blockIdx.x * 8 + (threadIdx.x >> 5);
    int lane = threadIdx.x & 31;

    const float4* Drow = (const float4*)(g_dists + (size_t)row * BNN);

    unsigned long long L[KSEL];
#pragma unroll
    for (int s = 0; s < KSEL; s++) L[s] = KSENT;
    float worstf = __uint_as_float(0x7f800000u);   // +INF
    int wpos = 0;

#pragma unroll 4
    for (int it = 0; it < 64; it++) {
        int vecidx = lane + (it << 5);
        float4 v = __ldcs(&Drow[vecidx]);
        float m = fminf(fminf(v.x, v.y), fminf(v.z, v.w));
        if (m < worstf) {
            unsigned j0 = (unsigned)(vecidx << 2);
            float f[4] = {v.x, v.y, v.z, v.w};
#pragma unroll
            for (int q = 0; q < 4; q++) {
                if (f[q] < worstf) {
                    unsigned long long key =
                        ((unsigned long long)ordkey(f[q]) << 32) | (j0 + (unsigned)q);
                    // replace current worst slot
#pragma unroll
                    for (int p = 0; p < KSEL; p++) if (p == wpos) L[p] = key;
                    // recompute worst
                    unsigned long long wk = L[0]; int np = 0;
#pragma unroll
                    for (int p = 1; p < KSEL; p++)
                        if (L[p] > wk) { wk = L[p]; np = p; }
                    wpos = np;
                    worstf = invordkey((unsigned)(wk >> 32));
                }
            }
        }
    }

    // sort the 11-entry list ascending (static compare-swap bubble)
#pragma unroll
    for (int i = 0; i < KSEL - 1; i++)
#pragma unroll
        for (int j = 0; j < KSEL - 1 - i; j++) {
            unsigned long long a = L[j], b = L[j + 1];
            bool sw = b < a;
            L[j]     = sw ? b : a;
            L[j + 1] = sw ? a : b;
        }

    // merge across lanes: 11 rounds of warp u64-min + owner pop
#pragma unroll 1
    for (int m = 0; m < KSEL; m++) {
        unsigned long long k = L[0];
#pragma unroll
        for (int off = 16; off; off >>= 1) {
            unsigned long long o = __shfl_xor_sync(0xffffffffu, k, off);
            if (o < k) k = o;
        }
        if (L[0] == k) {
            int idx = (int)(k & 0xffffffffu);
            g_inds[row * KSEL + m] = idx;
            atomicAdd(&g_de[idx], 1);
#pragma unroll
            for (int p = 0; p < KSEL - 1; p++) L[p] = L[p + 1];
            L[KSEL - 1] = KSENT;
        }
    }
}

// ---------------- kScat ----------------
__global__ __launch_bounds__(256) void kScat() {
    __shared__ int si[4 * KSEL];
    int tid = threadIdx.x;
    int node0 = blockIdx.x * 4;
    if (tid < 4 * KSEL) si[tid] = g_inds[node0 * KSEL + tid];
    __syncthreads();
    int n = tid >> 6, c = tid & 63;
    float uv = g_u[(node0 + n) * CC + c];
#pragma unroll
    for (int m = 0; m < KSEL; m++)
        atomicAdd(&g_sknn[si[n * KSEL + m] * CC + c], uv);
}

// ---------------- kLoc ----------------
__global__ __launch_bounds__(64) void kLoc() {
    int e = blockIdx.x;
    int c = threadIdx.x;
    int b  = e / 196, le = e % 196;
    int er = le / 14, ec = le % 14;
    int base = b * NROWS + er * 2 * 32 + ec * 2;
    float s = 0.0f;
#pragma unroll
    for (int dr = 0; dr < 5; dr++)
#pragma unroll
        for (int dc = 0; dc < 5; dc++)
            s += g_u[(base + dr * 32 + dc) * CC + c];
    g_sloc[e * CC + c] = s * (1.0f / 25.0f);
}

// ---------------- kScale ----------------
__global__ void kScale() {
    int i = blockIdx.x * 256 + threadIdx.x;
    int j = i >> 6;
    g_sknn[i] *= (1.0f / (float)g_de[j]);
}

// ---------------- kE: gather z + BN stats ----------------
__global__ __launch_bounds__(256) void kE() {
    __shared__ int si[4 * KSEL];
    __shared__ float red[256], red2[256];
    int tid = threadIdx.x;
    int node0 = blockIdx.x * 4;
    if (tid < 4 * KSEL) si[tid] = g_inds[node0 * KSEL + tid];
    __syncthreads();
    int n = tid >> 6, c = tid & 63;
    int node = node0 + n;

    float acc = 0.0f;
#pragma unroll
    for (int m = 0; m < KSEL; m++)
        acc += g_sknn[si[n * KSEL + m] * CC + c];

    int ln = node & (NROWS - 1);
    int r = ln >> 5, cc2 = ln & 31;
    int b = node >> 10;
    int sr0 = r - 4; if (sr0 < 0) sr0 = 0; sr0 += (sr0 & 1);
    int sr1 = r;     if (sr1 > 26) sr1 = 26; sr1 -= (sr1 & 1);
    int sc0 = cc2 - 4; if (sc0 < 0) sc0 = 0; sc0 += (sc0 & 1);
    int sc1 = cc2;     if (sc1 > 26) sc1 = 26; sc1 -= (sc1 & 1);
    for (int sr = sr0; sr <= sr1; sr += 2)
        for (int sc = sc0; sc <= sc1; sc += 2)
            acc += g_sloc[(b * 196 + (sr >> 1) * 14 + (sc >> 1)) * CC + c];

    float z = acc * dv2f(node);
    g_z[node * CC + c] = z;

    red[tid] = z; red2[tid] = z * z;
    __syncthreads();
    if (tid < 128) { red[tid] += red[tid + 128]; red2[tid] += red2[tid + 128]; }
    __syncthreads();
    if (tid < 64) {
        atomicAdd(&g_stats[tid],      red[tid]  + red[tid + 64]);
        atomicAdd(&g_stats[64 + tid], red2[tid] + red2[tid + 64]);
    }
}

// ---------------- kG ----------------
__global__ void kG(const float* __restrict__ x,
                   const float* __restrict__ gamma,
                   const float* __restrict__ beta,
                   float* __restrict__ out) {
    int i = blockIdx.x * 256 + threadIdx.x;
    int c = i & 63;
    float mu  = g_stats[c]      * (1.0f / (float)BNN);
    float ex2 = g_stats[64 + c] * (1.0f / (float)BNN);
    float var = ex2 - mu * mu;
    float rstd = 1.0f / sqrtf(var + 1e-5f);
    float zn = (g_z[i] - mu) * rstd * gamma[c] + beta[c];
    out[i] = fmaxf(zn, 0.0f) + x[i];
}

// ---------------- launch ----------------
extern "C" void kernel_launch(void* const* d_in, const int* in_sizes, int n_in,
                              void* d_out, int out_size) {
    const float* x     = (const float*)d_in[0];
    const float* W     = (const float*)d_in[1];
    const float* bconv = (const float*)d_in[2];
    const float* gamma = (const float*)d_in[3];
    const float* beta  = (const float*)d_in[4];
    float* out = (float*)d_out;

    const int SMEM_B = 2 * 64 * 129 * sizeof(float);
    cudaFuncSetAttribute(kB, cudaFuncAttributeMaxDynamicSharedMemorySize, SMEM_B);

    kZero <<<2048, 256>>>();
    kA    <<<BNN / 4, 256>>>(x, W, bconv);
    kB    <<<dim3(64, 64), 256, SMEM_B>>>(x);
    kC    <<<BNN / 8, 256>>>();
    kScat <<<BNN / 4, 256>>>();
    kLoc  <<<NLOC, 64>>>();
    kScale<<<2048, 256>>>();
    kE    <<<BNN / 4, 256>>>();
    kG    <<<2048, 256>>>(x, gamma, beta, out);
}

// round 5
// speedup vs baseline: 1.3516x; 1.3516x over previous
#include <cuda_runtime.h>
#include <math.h>

// ---------------- static problem config ----------------
#define BNN    8192
#define CC     64
#define KSEL   11
#define NLOC   1568
#define NROWS  1024
#define NSTRIP 8
#define STRIPL 1024     // columns per strip

// ---------------- device scratch ----------------
__device__ float g_dists[(size_t)BNN * BNN];
__device__ float g_u[BNN * CC];
__device__ float g_sq[BNN];
__device__ int   g_inds[BNN * KSEL];
__device__ int   g_de[BNN];
__device__ float g_sknn[BNN * CC];
__device__ float g_sloc[NLOC * CC];
__device__ float g_z[BNN * CC];
__device__ float g_stats[2 * CC];
__device__ unsigned long long g_cand[(size_t)BNN * NSTRIP * KSEL];  // per-strip top-11

// ---------------- helpers ----------------
__device__ __forceinline__ int covdim(int r) {
    int lo = r - 4; if (lo < 0) lo = 0;
    int hi = r;     if (hi > 26) hi = 26;
    if (hi < lo) return 0;
    return hi / 2 - (lo + 1) / 2 + 1;
}

__device__ __forceinline__ float dv2f(int node) {
    int ln = node & (NROWS - 1);
    int r = ln >> 5, c = ln & 31;
    int deg = covdim(r) * covdim(c);
    return 1.0f / sqrtf((float)(KSEL + deg));
}

__device__ __forceinline__ unsigned ordkey(float f) {
    unsigned u = __float_as_uint(f);
    return (u & 0x80000000u) ? ~u : (u | 0x80000000u);
}
__device__ __forceinline__ float invordkey(unsigned k) {
    unsigned u = (k & 0x80000000u) ? (k ^ 0x80000000u) : ~k;
    return __uint_as_float(u);
}

// sentinel: value=+INF, index=0xFFFFFFFF
#define KSENT 0xFF800000FFFFFFFFull

// ---------------- kZero ----------------
__global__ void kZero() {
    int i = blockIdx.x * 256 + threadIdx.x;
    if (i < BNN * CC) g_sknn[i] = 0.0f;
    if (i < BNN)      g_de[i]   = 0;
    if (i < 2 * CC)   g_stats[i] = 0.0f;
}

// ---------------- kA: sq norms + u = dv2 * (x W^T + b) ----------------
__global__ __launch_bounds__(256) void kA(const float* __restrict__ x,
                                          const float* __restrict__ W,
                                          const float* __restrict__ bconv) {
    __shared__ float Ws[CC][CC + 1];
    __shared__ float xs[4][CC];
    __shared__ float red[256];
    int tid = threadIdx.x;
    int node0 = blockIdx.x * 4;

    for (int i = tid; i < CC * CC; i += 256) Ws[i >> 6][i & 63] = W[i];
    for (int i = tid; i < 4 * CC; i += 256) xs[i >> 6][i & 63] = x[node0 * CC + i];
    __syncthreads();

    int n = tid >> 6, c = tid & 63;
    int node = node0 + n;

    float v = xs[n][c];
    red[tid] = v * v;
    __syncthreads();
    if (c < 32) red[tid] += red[tid + 32]; __syncthreads();
    if (c < 16) red[tid] += red[tid + 16]; __syncthreads();
    if (c < 8)  red[tid] += red[tid + 8];  __syncthreads();
    if (c < 4)  red[tid] += red[tid + 4];  __syncthreads();
    if (c < 2)  red[tid] += red[tid + 2];  __syncthreads();
    if (c < 1)  red[tid] += red[tid + 1];  __syncthreads();
    if (c == 0) g_sq[node] = red[tid];

    float acc = bconv[c];
#pragma unroll
    for (int k = 0; k < CC; k++) acc += xs[n][k] * Ws[c][k];
    g_u[node * CC + c] = acc * dv2f(node);
}

// ---------------- kB: fp32 distance GEMM (exactly symmetric output) ----------------
__global__ __launch_bounds__(256, 2) void kB(const float* __restrict__ x) {
    extern __shared__ float sm[];
    float (*As)[129] = (float (*)[129])sm;
    float (*Bs)[129] = (float (*)[129])(sm + 64 * 129);

    int ib = blockIdx.y, jb = blockIdx.x;
    int tid = threadIdx.x;

#pragma unroll
    for (int it = 0; it < 8; it++) {
        int idx = tid + it * 256;
        int r   = idx >> 4;
        int k4  = (idx & 15) * 4;
        float4 va = *(const float4*)(x + (size_t)(ib * 128 + r) * CC + k4);
        As[k4 + 0][r] = va.x; As[k4 + 1][r] = va.y;
        As[k4 + 2][r] = va.z; As[k4 + 3][r] = va.w;
        float4 vb = *(const float4*)(x + (size_t)(jb * 128 + r) * CC + k4);
        Bs[k4 + 0][r] = vb.x; Bs[k4 + 1][r] = vb.y;
        Bs[k4 + 2][r] = vb.z; Bs[k4 + 3][r] = vb.w;
    }
    __syncthreads();

    int tx = tid & 31;
    int ty = tid >> 5;

    float acc[16][4];
#pragma unroll
    for (int i = 0; i < 16; i++)
#pragma unroll
        for (int j = 0; j < 4; j++) acc[i][j] = 0.0f;

#pragma unroll 4
    for (int k = 0; k < 64; k++) {
        float a[16], b[4];
#pragma unroll
        for (int i = 0; i < 16; i++) a[i] = As[k][ty * 16 + i];
#pragma unroll
        for (int j = 0; j < 4; j++)  b[j] = Bs[k][tx + 32 * j];
#pragma unroll
        for (int i = 0; i < 16; i++)
#pragma unroll
            for (int j = 0; j < 4; j++) acc[i][j] += a[i] * b[j];
    }

    float sqi[16], sqj[4];
#pragma unroll
    for (int i = 0; i < 16; i++) sqi[i] = g_sq[ib * 128 + ty * 16 + i];
#pragma unroll
    for (int j = 0; j < 4; j++)  sqj[j] = g_sq[jb * 128 + tx + 32 * j];

#pragma unroll
    for (int i = 0; i < 16; i++) {
        size_t rowoff = (size_t)(ib * 128 + ty * 16 + i) * BNN;
#pragma unroll
        for (int j = 0; j < 4; j++) {
            int col = jb * 128 + tx + 32 * j;
            g_dists[rowoff + col] = sqi[i] + sqj[j] - 2.0f * acc[i][j];
        }
    }
}

// ---------------- kCs: thread-per-(row,strip) column scan, coalesced ----------------
// D is exactly symmetric, so scanning column r over rows j gives row r's distances.
__global__ __launch_bounds__(256) void kCs() {
    int t = blockIdx.x * 256 + threadIdx.x;   // 65536 threads
    int row   = t & (BNN - 1);
    int strip = t >> 13;

    const float* p = g_dists + (size_t)(strip * STRIPL) * BNN + row;

    unsigned long long L[KSEL];
#pragma unroll
    for (int s = 0; s < KSEL; s++) L[s] = KSENT;
    float worstf = __uint_as_float(0x7f800000u);   // +INF

#pragma unroll 1
    for (int s = 0; s < STRIPL / 16; s++) {
        const float* ps = p + (size_t)s * 16 * BNN;
        float f[16];
#pragma unroll
        for (int q = 0; q < 16; q++) f[q] = __ldcs(ps + (size_t)q * BNN);

        float m01 = fminf(f[0], f[1]),  m23 = fminf(f[2], f[3]);
        float m45 = fminf(f[4], f[5]),  m67 = fminf(f[6], f[7]);
        float m89 = fminf(f[8], f[9]),  mab = fminf(f[10], f[11]);
        float mcd = fminf(f[12], f[13]), mef = fminf(f[14], f[15]);
        float m = fminf(fminf(fminf(m01, m23), fminf(m45, m67)),
                        fminf(fminf(m89, mab), fminf(mcd, mef)));
        if (m <= worstf) {
            unsigned jbase = (unsigned)(strip * STRIPL + s * 16);
#pragma unroll
            for (int q = 0; q < 16; q++) {
                if (f[q] <= worstf) {
                    unsigned long long key =
                        ((unsigned long long)ordkey(f[q]) << 32) | (jbase + (unsigned)q);
                    if (key < L[KSEL - 1]) {
                        L[KSEL - 1] = key;
#pragma unroll
                        for (int pp = KSEL - 1; pp > 0; --pp) {
                            unsigned long long a = L[pp - 1], b = L[pp];
                            bool sw = b < a;
                            L[pp - 1] = sw ? b : a;
                            L[pp]     = sw ? a : b;
                        }
                        worstf = invordkey((unsigned)(L[KSEL - 1] >> 32));
                    }
                }
            }
        }
    }

    unsigned long long* out = g_cand + (size_t)t * KSEL;
#pragma unroll
    for (int s = 0; s < KSEL; s++) out[s] = L[s];
}

// ---------------- kC2: warp-per-row merge of 8 strip lists (88 keys) ----------------
__global__ __launch_bounds__(256) void kC2() {
    int row  = blockIdx.x * 8 + (threadIdx.x >> 5);
    int lane = threadIdx.x & 31;

    unsigned long long c0 = KSENT, c1 = KSENT, c2 = KSENT;
    {
        int pos = lane;               // 0..31
        int strip = pos / KSEL, k = pos % KSEL;
        c0 = g_cand[((size_t)(strip * BNN + row)) * KSEL + k];
    }
    {
        int pos = lane + 32;          // 32..63
        int strip = pos / KSEL, k = pos % KSEL;
        c1 = g_cand[((size_t)(strip * BNN + row)) * KSEL + k];
    }
    if (lane < 24) {
        int pos = lane + 64;          // 64..87
        int strip = pos / KSEL, k = pos % KSEL;
        c2 = g_cand[((size_t)(strip * BNN + row)) * KSEL + k];
    }
    // sort3 ascending
    {
        unsigned long long a, b;
        a = c0; b = c1; c0 = a < b ? a : b; c1 = a < b ? b : a;
        a = c1; b = c2; c1 = a < b ? a : b; c2 = a < b ? b : a;
        a = c0; b = c1; c0 = a < b ? a : b; c1 = a < b ? b : a;
    }

#pragma unroll 1
    for (int m = 0; m < KSEL; m++) {
        unsigned long long k = c0;
#pragma unroll
        for (int off = 16; off; off >>= 1) {
            unsigned long long o = __shfl_xor_sync(0xffffffffu, k, off);
            if (o < k) k = o;
        }
        if (c0 == k) {                // unique owner: indices are distinct
            int idx = (int)(k & 0xffffffffu);
            g_inds[row * KSEL + m] = idx;
            atomicAdd(&g_de[idx], 1);
            c0 = c1; c1 = c2; c2 = KSENT;
        }
    }
}

// ---------------- kScat ----------------
__global__ __launch_bounds__(256) void kScat() {
    __shared__ int si[4 * KSEL];
    int tid = threadIdx.x;
    int node0 = blockIdx.x * 4;
    if (tid < 4 * KSEL) si[tid] = g_inds[node0 * KSEL + tid];
    __syncthreads();
    int n = tid >> 6, c = tid & 63;
    float uv = g_u[(node0 + n) * CC + c];
#pragma unroll
    for (int m = 0; m < KSEL; m++)
        atomicAdd(&g_sknn[si[n * KSEL + m] * CC + c], uv);
}

// ---------------- kLoc ----------------
__global__ __launch_bounds__(64) void kLoc() {
    int e = blockIdx.x;
    int c = threadIdx.x;
    int b  = e / 196, le = e % 196;
    int er = le / 14, ec = le % 14;
    int base = b * NROWS + er * 2 * 32 + ec * 2;
    float s = 0.0f;
#pragma unroll
    for (int dr = 0; dr < 5; dr++)
#pragma unroll
        for (int dc = 0; dc < 5; dc++)
            s += g_u[(base + dr * 32 + dc) * CC + c];
    g_sloc[e * CC + c] = s * (1.0f / 25.0f);
}

// ---------------- kScale ----------------
__global__ void kScale() {
    int i = blockIdx.x * 256 + threadIdx.x;
    int j = i >> 6;
    g_sknn[i] *= (1.0f / (float)g_de[j]);
}

// ---------------- kE: gather z + BN stats ----------------
__global__ __launch_bounds__(256) void kE() {
    __shared__ int si[4 * KSEL];
    __shared__ float red[256], red2[256];
    int tid = threadIdx.x;
    int node0 = blockIdx.x * 4;
    if (tid < 4 * KSEL) si[tid] = g_inds[node0 * KSEL + tid];
    __syncthreads();
    int n = tid >> 6, c = tid & 63;
    int node = node0 + n;

    float acc = 0.0f;
#pragma unroll
    for (int m = 0; m < KSEL; m++)
        acc += g_sknn[si[n * KSEL + m] * CC + c];

    int ln = node & (NROWS - 1);
    int r = ln >> 5, cc2 = ln & 31;
    int b = node >> 10;
    int sr0 = r - 4; if (sr0 < 0) sr0 = 0; sr0 += (sr0 & 1);
    int sr1 = r;     if (sr1 > 26) sr1 = 26; sr1 -= (sr1 & 1);
    int sc0 = cc2 - 4; if (sc0 < 0) sc0 = 0; sc0 += (sc0 & 1);
    int sc1 = cc2;     if (sc1 > 26) sc1 = 26; sc1 -= (sc1 & 1);
    for (int sr = sr0; sr <= sr1; sr += 2)
        for (int sc = sc0; sc <= sc1; sc += 2)
            acc += g_sloc[(b * 196 + (sr >> 1) * 14 + (sc >> 1)) * CC + c];

    float z = acc * dv2f(node);
    g_z[node * CC + c] = z;

    red[tid] = z; red2[tid] = z * z;
    __syncthreads();
    if (tid < 128) { red[tid] += red[tid + 128]; red2[tid] += red2[tid + 128]; }
    __syncthreads();
    if (tid < 64) {
        atomicAdd(&g_stats[tid],      red[tid]  + red[tid + 64]);
        atomicAdd(&g_stats[64 + tid], red2[tid] + red2[tid + 64]);
    }
}

// ---------------- kG ----------------
__global__ void kG(const float* __restrict__ x,
                   const float* __restrict__ gamma,
                   const float* __restrict__ beta,
                   float* __restrict__ out) {
    int i = blockIdx.x * 256 + threadIdx.x;
    int c = i & 63;
    float mu  = g_stats[c]      * (1.0f / (float)BNN);
    float ex2 = g_stats[64 + c] * (1.0f / (float)BNN);
    float var = ex2 - mu * mu;
    float rstd = 1.0f / sqrtf(var + 1e-5f);
    float zn = (g_z[i] - mu) * rstd * gamma[c] + beta[c];
    out[i] = fmaxf(zn, 0.0f) + x[i];
}

// ---------------- launch ----------------
extern "C" void kernel_launch(void* const* d_in, const int* in_sizes, int n_in,
                              void* d_out, int out_size) {
    const float* x     = (const float*)d_in[0];
    const float* W     = (const float*)d_in[1];
    const float* bconv = (const float*)d_in[2];
    const float* gamma = (const float*)d_in[3];
    const float* beta  = (const float*)d_in[4];
    float* out = (float*)d_out;

    const int SMEM_B = 2 * 64 * 129 * sizeof(float);
    cudaFuncSetAttribute(kB, cudaFuncAttributeMaxDynamicSharedMemorySize, SMEM_B);

    kZero <<<2048, 256>>>();
    kA    <<<BNN / 4, 256>>>(x, W, bconv);
    kB    <<<dim3(64, 64), 256, SMEM_B>>>(x);
    kCs   <<<BNN * NSTRIP / 256, 256>>>();
    kC2   <<<BNN / 8, 256>>>();
    kScat <<<BNN / 4, 256>>>();
    kLoc  <<<NLOC, 64>>>();
    kScale<<<2048, 256>>>();
    kE    <<<BNN / 4, 256>>>();
    kG    <<<2048, 256>>>(x, gamma, beta, out);
}

// round 6
// speedup vs baseline: 1.4151x; 1.0470x over previous
#include <cuda_runtime.h>
#include <math.h>

// ---------------- static problem config ----------------
#define BNN    8192
#define CC     64
#define KSEL   11
#define NLOC   1568
#define NROWS  1024
#define NSTRIP 32
#define STRIPL 256      // columns per strip

// ---------------- device scratch ----------------
__device__ float g_dists[(size_t)BNN * BNN];
__device__ float g_u[BNN * CC];
__device__ float g_sq[BNN];
__device__ int   g_inds[BNN * KSEL];
__device__ int   g_de[BNN];
__device__ float g_sknn[BNN * CC];
__device__ float g_sloc[NLOC * CC];
__device__ float g_z[BNN * CC];
__device__ float g_stats[2 * CC];
__device__ unsigned long long g_cand[(size_t)BNN * NSTRIP * KSEL];

// ---------------- helpers ----------------
__device__ __forceinline__ int covdim(int r) {
    int lo = r - 4; if (lo < 0) lo = 0;
    int hi = r;     if (hi > 26) hi = 26;
    if (hi < lo) return 0;
    return hi / 2 - (lo + 1) / 2 + 1;
}

__device__ __forceinline__ float dv2f(int node) {
    int ln = node & (NROWS - 1);
    int r = ln >> 5, c = ln & 31;
    int deg = covdim(r) * covdim(c);
    return 1.0f / sqrtf((float)(KSEL + deg));
}

__device__ __forceinline__ unsigned ordkey(float f) {
    unsigned u = __float_as_uint(f);
    return (u & 0x80000000u) ? ~u : (u | 0x80000000u);
}
__device__ __forceinline__ float invordkey(unsigned k) {
    unsigned u = (k & 0x80000000u) ? (k ^ 0x80000000u) : ~k;
    return __uint_as_float(u);
}

// sentinel: value=+INF, index=0xFFFFFFFF
#define KSENT 0xFF800000FFFFFFFFull

// ---------------- kZero ----------------
__global__ void kZero() {
    int i = blockIdx.x * 256 + threadIdx.x;
    if (i < BNN * CC) g_sknn[i] = 0.0f;
    if (i < BNN)      g_de[i]   = 0;
    if (i < 2 * CC)   g_stats[i] = 0.0f;
}

// ---------------- kA: sq norms + u = dv2 * (x W^T + b) ----------------
__global__ __launch_bounds__(256) void kA(const float* __restrict__ x,
                                          const float* __restrict__ W,
                                          const float* __restrict__ bconv) {
    __shared__ float Ws[CC][CC + 1];
    __shared__ float xs[4][CC];
    __shared__ float red[256];
    int tid = threadIdx.x;
    int node0 = blockIdx.x * 4;

    for (int i = tid; i < CC * CC; i += 256) Ws[i >> 6][i & 63] = W[i];
    for (int i = tid; i < 4 * CC; i += 256) xs[i >> 6][i & 63] = x[node0 * CC + i];
    __syncthreads();

    int n = tid >> 6, c = tid & 63;
    int node = node0 + n;

    float v = xs[n][c];
    red[tid] = v * v;
    __syncthreads();
    if (c < 32) red[tid] += red[tid + 32]; __syncthreads();
    if (c < 16) red[tid] += red[tid + 16]; __syncthreads();
    if (c < 8)  red[tid] += red[tid + 8];  __syncthreads();
    if (c < 4)  red[tid] += red[tid + 4];  __syncthreads();
    if (c < 2)  red[tid] += red[tid + 2];  __syncthreads();
    if (c < 1)  red[tid] += red[tid + 1];  __syncthreads();
    if (c == 0) g_sq[node] = red[tid];

    float acc = bconv[c];
#pragma unroll
    for (int k = 0; k < CC; k++) acc += xs[n][k] * Ws[c][k];
    g_u[node * CC + c] = acc * dv2f(node);
}

// ---------------- kB: upper-triangle fp32 distance GEMM + smem-transposed mirror ----------------
__global__ __launch_bounds__(256, 2) void kB(const float* __restrict__ x) {
    extern __shared__ float sm[];
    float (*As)[129] = (float (*)[129])sm;                 // 64x129
    float (*Bs)[129] = (float (*)[129])(sm + 64 * 129);    // 64x129
    float (*Ts)[129] = (float (*)[129])sm;                 // reuse: 128x129 transpose buf

    int ib = blockIdx.y, jb = blockIdx.x;
    if (jb < ib) return;
    int tid = threadIdx.x;

#pragma unroll
    for (int it = 0; it < 8; it++) {
        int idx = tid + it * 256;
        int r   = idx >> 4;
        int k4  = (idx & 15) * 4;
        float4 va = *(const float4*)(x + (size_t)(ib * 128 + r) * CC + k4);
        As[k4 + 0][r] = va.x; As[k4 + 1][r] = va.y;
        As[k4 + 2][r] = va.z; As[k4 + 3][r] = va.w;
        float4 vb = *(const float4*)(x + (size_t)(jb * 128 + r) * CC + k4);
        Bs[k4 + 0][r] = vb.x; Bs[k4 + 1][r] = vb.y;
        Bs[k4 + 2][r] = vb.z; Bs[k4 + 3][r] = vb.w;
    }
    __syncthreads();

    int tx = tid & 31;
    int ty = tid >> 5;

    float acc[16][4];
#pragma unroll
    for (int i = 0; i < 16; i++)
#pragma unroll
        for (int j = 0; j < 4; j++) acc[i][j] = 0.0f;

#pragma unroll 4
    for (int k = 0; k < 64; k++) {
        float a[16], b[4];
#pragma unroll
        for (int i = 0; i < 16; i++) a[i] = As[k][ty * 16 + i];
#pragma unroll
        for (int j = 0; j < 4; j++)  b[j] = Bs[k][tx + 32 * j];
#pragma unroll
        for (int i = 0; i < 16; i++)
#pragma unroll
            for (int j = 0; j < 4; j++) acc[i][j] += a[i] * b[j];
    }

    float sqi[16], sqj[4];
#pragma unroll
    for (int i = 0; i < 16; i++) sqi[i] = g_sq[ib * 128 + ty * 16 + i];
#pragma unroll
    for (int j = 0; j < 4; j++)  sqj[j] = g_sq[jb * 128 + tx + 32 * j];

    // finalize distances in-place, direct store
#pragma unroll
    for (int i = 0; i < 16; i++) {
        size_t rowoff = (size_t)(ib * 128 + ty * 16 + i) * BNN;
#pragma unroll
        for (int j = 0; j < 4; j++) {
            acc[i][j] = sqi[i] + sqj[j] - 2.0f * acc[i][j];
            g_dists[rowoff + jb * 128 + tx + 32 * j] = acc[i][j];
        }
    }

    if (jb > ib) {
        __syncthreads();   // done reading As/Bs
#pragma unroll
        for (int i = 0; i < 16; i++)
#pragma unroll
            for (int j = 0; j < 4; j++)
                Ts[ty * 16 + i][tx + 32 * j] = acc[i][j];
        __syncthreads();
        // mirrored tile: rows jb*128+c', cols ib*128+r'
#pragma unroll
        for (int i = 0; i < 16; i++) {
            int cp = ty * 16 + i;
            size_t rowoff = (size_t)(jb * 128 + cp) * BNN;
#pragma unroll
            for (int j = 0; j < 4; j++) {
                int rp = tx + 32 * j;
                g_dists[rowoff + ib * 128 + rp] = Ts[rp][cp];
            }
        }
    }
}

// ---------------- kCs: thread-per-(row,strip) column scan, coalesced ----------------
__global__ __launch_bounds__(256) void kCs() {
    int t = blockIdx.x * 256 + threadIdx.x;   // 262144 threads
    int row   = t & (BNN - 1);
    int strip = t >> 13;

    const float* p = g_dists + (size_t)(strip * STRIPL) * BNN + row;

    unsigned long long L[KSEL];
#pragma unroll
    for (int s = 0; s < KSEL; s++) L[s] = KSENT;
    float worstf = __uint_as_float(0x7f800000u);   // +INF

#pragma unroll 1
    for (int s = 0; s < STRIPL / 16; s++) {
        const float* ps = p + (size_t)s * 16 * BNN;
        float f[16];
#pragma unroll
        for (int q = 0; q < 16; q++) f[q] = __ldcs(ps + (size_t)q * BNN);

        float m01 = fminf(f[0], f[1]),  m23 = fminf(f[2], f[3]);
        float m45 = fminf(f[4], f[5]),  m67 = fminf(f[6], f[7]);
        float m89 = fminf(f[8], f[9]),  mab = fminf(f[10], f[11]);
        float mcd = fminf(f[12], f[13]), mef = fminf(f[14], f[15]);
        float m = fminf(fminf(fminf(m01, m23), fminf(m45, m67)),
                        fminf(fminf(m89, mab), fminf(mcd, mef)));
        if (m <= worstf) {
            unsigned jbase = (unsigned)(strip * STRIPL + s * 16);
#pragma unroll
            for (int q = 0; q < 16; q++) {
                if (f[q] <= worstf) {
                    unsigned long long key =
                        ((unsigned long long)ordkey(f[q]) << 32) | (jbase + (unsigned)q);
                    if (key < L[KSEL - 1]) {
                        L[KSEL - 1] = key;
#pragma unroll
                        for (int pp = KSEL - 1; pp > 0; --pp) {
                            unsigned long long a = L[pp - 1], b = L[pp];
                            bool sw = b < a;
                            L[pp - 1] = sw ? b : a;
                            L[pp]     = sw ? a : b;
                        }
                        worstf = invordkey((unsigned)(L[KSEL - 1] >> 32));
                    }
                }
            }
        }
    }

    unsigned long long* out = g_cand + (size_t)t * KSEL;
#pragma unroll
    for (int s = 0; s < KSEL; s++) out[s] = L[s];
}

// ---------------- kC2: warp-per-row merge of 32 sorted strip lists ----------------
__global__ __launch_bounds__(256) void kC2() {
    int row  = blockIdx.x * 8 + (threadIdx.x >> 5);
    int lane = threadIdx.x & 31;       // lane == strip

    unsigned long long L[KSEL];
    const unsigned long long* src = g_cand + ((size_t)(lane * BNN + row)) * KSEL;
#pragma unroll
    for (int k = 0; k < KSEL; k++) L[k] = src[k];   // already sorted ascending

#pragma unroll 1
    for (int m = 0; m < KSEL; m++) {
        unsigned long long k = L[0];
#pragma unroll
        for (int off = 16; off; off >>= 1) {
            unsigned long long o = __shfl_xor_sync(0xffffffffu, k, off);
            if (o < k) k = o;
        }
        if (L[0] == k) {               // unique owner (distinct indices)
            int idx = (int)(k & 0xffffffffu);
            g_inds[row * KSEL + m] = idx;
            atomicAdd(&g_de[idx], 1);
#pragma unroll
            for (int p = 0; p < KSEL - 1; p++) L[p] = L[p + 1];
            L[KSEL - 1] = KSENT;
        }
    }
}

// ---------------- kScat ----------------
__global__ __launch_bounds__(256) void kScat() {
    __shared__ int si[4 * KSEL];
    int tid = threadIdx.x;
    int node0 = blockIdx.x * 4;
    if (tid < 4 * KSEL) si[tid] = g_inds[node0 * KSEL + tid];
    __syncthreads();
    int n = tid >> 6, c = tid & 63;
    float uv = g_u[(node0 + n) * CC + c];
#pragma unroll
    for (int m = 0; m < KSEL; m++)
        atomicAdd(&g_sknn[si[n * KSEL + m] * CC + c], uv);
}

// ---------------- kLoc ----------------
__global__ __launch_bounds__(64) void kLoc() {
    int e = blockIdx.x;
    int c = threadIdx.x;
    int b  = e / 196, le = e % 196;
    int er = le / 14, ec = le % 14;
    int base = b * NROWS + er * 2 * 32 + ec * 2;
    float s = 0.0f;
#pragma unroll
    for (int dr = 0; dr < 5; dr++)
#pragma unroll
        for (int dc = 0; dc < 5; dc++)
            s += g_u[(base + dr * 32 + dc) * CC + c];
    g_sloc[e * CC + c] = s * (1.0f / 25.0f);
}

// ---------------- kScale ----------------
__global__ void kScale() {
    int i = blockIdx.x * 256 + threadIdx.x;
    int j = i >> 6;
    g_sknn[i] *= (1.0f / (float)g_de[j]);
}

// ---------------- kE: gather z + BN stats ----------------
__global__ __launch_bounds__(256) void kE() {
    __shared__ int si[4 * KSEL];
    __shared__ float red[256], red2[256];
    int tid = threadIdx.x;
    int node0 = blockIdx.x * 4;
    if (tid < 4 * KSEL) si[tid] = g_inds[node0 * KSEL + tid];
    __syncthreads();
    int n = tid >> 6, c = tid & 63;
    int node = node0 + n;

    float acc = 0.0f;
#pragma unroll
    for (int m = 0; m < KSEL; m++)
        acc += g_sknn[si[n * KSEL + m] * CC + c];

    int ln = node & (NROWS - 1);
    int r = ln >> 5, cc2 = ln & 31;
    int b = node >> 10;
    int sr0 = r - 4; if (sr0 < 0) sr0 = 0; sr0 += (sr0 & 1);
    int sr1 = r;     if (sr1 > 26) sr1 = 26; sr1 -= (sr1 & 1);
    int sc0 = cc2 - 4; if (sc0 < 0) sc0 = 0; sc0 += (sc0 & 1);
    int sc1 = cc2;     if (sc1 > 26) sc1 = 26; sc1 -= (sc1 & 1);
    for (int sr = sr0; sr <= sr1; sr += 2)
        for (int sc = sc0; sc <= sc1; sc += 2)
            acc += g_sloc[(b * 196 + (sr >> 1) * 14 + (sc >> 1)) * CC + c];

    float z = acc * dv2f(node);
    g_z[node * CC + c] = z;

    red[tid] = z; red2[tid] = z * z;
    __syncthreads();
    if (tid < 128) { red[tid] += red[tid + 128]; red2[tid] += red2[tid + 128]; }
    __syncthreads();
    if (tid < 64) {
        atomicAdd(&g_stats[tid],      red[tid]  + red[tid + 64]);
        atomicAdd(&g_stats[64 + tid], red2[tid] + red2[tid + 64]);
    }
}

// ---------------- kG ----------------
__global__ void kG(const float* __restrict__ x,
                   const float* __restrict__ gamma,
                   const float* __restrict__ beta,
                   float* __restrict__ out) {
    int i = blockIdx.x * 256 + threadIdx.x;
    int c = i & 63;
    float mu  = g_stats[c]      * (1.0f / (float)BNN);
    float ex2 = g_stats[64 + c] * (1.0f / (float)BNN);
    float var = ex2 - mu * mu;
    float rstd = 1.0f / sqrtf(var + 1e-5f);
    float zn = (g_z[i] - mu) * rstd * gamma[c] + beta[c];
    out[i] = fmaxf(zn, 0.0f) + x[i];
}

// ---------------- launch ----------------
extern "C" void kernel_launch(void* const* d_in, const int* in_sizes, int n_in,
                              void* d_out, int out_size) {
    const float* x     = (const float*)d_in[0];
    const float* W     = (const float*)d_in[1];
    const float* bconv = (const float*)d_in[2];
    const float* gamma = (const float*)d_in[3];
    const float* beta  = (const float*)d_in[4];
    float* out = (float*)d_out;

    const int SMEM_B = 2 * 64 * 129 * sizeof(float);   // 66048 B (= 128*129 floats)
    cudaFuncSetAttribute(kB, cudaFuncAttributeMaxDynamicSharedMemorySize, SMEM_B);

    kZero <<<2048, 256>>>();
    kA    <<<BNN / 4, 256>>>(x, W, bconv);
    kB    <<<dim3(64, 64), 256, SMEM_B>>>(x);
    kCs   <<<BNN * NSTRIP / 256, 256>>>();
    kC2   <<<BNN / 8, 256>>>();
    kScat <<<BNN / 4, 256>>>();
    kLoc  <<<NLOC, 64>>>();
    kScale<<<2048, 256>>>();
    kE    <<<BNN / 4, 256>>>();
    kG    <<<2048, 256>>>(x, gamma, beta, out);
}

// round 8
// speedup vs baseline: 2.0054x; 1.4171x over previous
#include <cuda_runtime.h>
#include <math.h>

// ---------------- static problem config ----------------
#define BNN    8192
#define CC     64
#define KSEL   11
#define NLOC   1568
#define NROWS  1024

// ---------------- device scratch ----------------
__device__ float g_dists[(size_t)BNN * BNN];
__device__ float g_u[BNN * CC];
__device__ float g_sq[BNN];
__device__ int   g_inds[BNN * KSEL];
__device__ int   g_de[BNN];
__device__ float g_sknn[BNN * CC];
__device__ float g_sloc[NLOC * CC];
__device__ float g_z[BNN * CC];
__device__ float g_stats[2 * CC];

// ---------------- helpers ----------------
__device__ __forceinline__ int covdim(int r) {
    int lo = r - 4; if (lo < 0) lo = 0;
    int hi = r;     if (hi > 26) hi = 26;
    if (hi < lo) return 0;
    return hi / 2 - (lo + 1) / 2 + 1;
}

__device__ __forceinline__ float dv2f(int node) {
    int ln = node & (NROWS - 1);
    int r = ln >> 5, c = ln & 31;
    int deg = covdim(r) * covdim(c);
    return 1.0f / sqrtf((float)(KSEL + deg));
}

__device__ __forceinline__ unsigned ordkey(float f) {
    unsigned u = __float_as_uint(f);
    return (u & 0x80000000u) ? ~u : (u | 0x80000000u);
}
__device__ __forceinline__ float invordkey(unsigned k) {
    unsigned u = (k & 0x80000000u) ? (k ^ 0x80000000u) : ~k;
    return __uint_as_float(u);
}

#define KSENT 0xFF800000FFFFFFFFull

// ---------------- kZero ----------------
__global__ void kZero() {
    int i = blockIdx.x * 256 + threadIdx.x;
    if (i < BNN * CC) g_sknn[i] = 0.0f;
    if (i < BNN)      g_de[i]   = 0;
    if (i < 2 * CC)   g_stats[i] = 0.0f;
}

// ---------------- kA: sq norms + u = dv2 * (x W^T + b) ----------------
__global__ __launch_bounds__(256) void kA(const float* __restrict__ x,
                                          const float* __restrict__ W,
                                          const float* __restrict__ bconv) {
    __shared__ float Ws[CC][CC + 1];
    __shared__ float xs[4][CC];
    __shared__ float red[256];
    int tid = threadIdx.x;
    int node0 = blockIdx.x * 4;

    for (int i = tid; i < CC * CC; i += 256) Ws[i >> 6][i & 63] = W[i];
    for (int i = tid; i < 4 * CC; i += 256) xs[i >> 6][i & 63] = x[node0 * CC + i];
    __syncthreads();

    int n = tid >> 6, c = tid & 63;
    int node = node0 + n;

    float v = xs[n][c];
    red[tid] = v * v;
    __syncthreads();
    if (c < 32) red[tid] += red[tid + 32]; __syncthreads();
    if (c < 16) red[tid] += red[tid + 16]; __syncthreads();
    if (c < 8)  red[tid] += red[tid + 8];  __syncthreads();
    if (c < 4)  red[tid] += red[tid + 4];  __syncthreads();
    if (c < 2)  red[tid] += red[tid + 2];  __syncthreads();
    if (c < 1)  red[tid] += red[tid + 1];  __syncthreads();
    if (c == 0) g_sq[node] = red[tid];

    float acc = bconv[c];
#pragma unroll
    for (int k = 0; k < CC; k++) acc += xs[n][k] * Ws[c][k];
    g_u[node * CC + c] = acc * dv2f(node);
}

// ---------------- kB: upper-triangle fp32 distance GEMM + smem-transposed mirror ----------------
__global__ __launch_bounds__(256, 2) void kB(const float* __restrict__ x) {
    extern __shared__ float sm[];
    float (*As)[129] = (float (*)[129])sm;
    float (*Bs)[129] = (float (*)[129])(sm + 64 * 129);
    float (*Ts)[129] = (float (*)[129])sm;

    int ib = blockIdx.y, jb = blockIdx.x;
    if (jb < ib) return;
    int tid = threadIdx.x;

#pragma unroll
    for (int it = 0; it < 8; it++) {
        int idx = tid + it * 256;
        int r   = idx >> 4;
        int k4  = (idx & 15) * 4;
        float4 va = *(const float4*)(x + (size_t)(ib * 128 + r) * CC + k4);
        As[k4 + 0][r] = va.x; As[k4 + 1][r] = va.y;
        As[k4 + 2][r] = va.z; As[k4 + 3][r] = va.w;
        float4 vb = *(const float4*)(x + (size_t)(jb * 128 + r) * CC + k4);
        Bs[k4 + 0][r] = vb.x; Bs[k4 + 1][r] = vb.y;
        Bs[k4 + 2][r] = vb.z; Bs[k4 + 3][r] = vb.w;
    }
    __syncthreads();

    int tx = tid & 31;
    int ty = tid >> 5;

    float acc[16][4];
#pragma unroll
    for (int i = 0; i < 16; i++)
#pragma unroll
        for (int j = 0; j < 4; j++) acc[i][j] = 0.0f;

#pragma unroll 4
    for (int k = 0; k < 64; k++) {
        float a[16], b[4];
#pragma unroll
        for (int i = 0; i < 16; i++) a[i] = As[k][ty * 16 + i];
#pragma unroll
        for (int j = 0; j < 4; j++)  b[j] = Bs[k][tx + 32 * j];
#pragma unroll
        for (int i = 0; i < 16; i++)
#pragma unroll
            for (int j = 0; j < 4; j++) acc[i][j] += a[i] * b[j];
    }

    float sqi[16], sqj[4];
#pragma unroll
    for (int i = 0; i < 16; i++) sqi[i] = g_sq[ib * 128 + ty * 16 + i];
#pragma unroll
    for (int j = 0; j < 4; j++)  sqj[j] = g_sq[jb * 128 + tx + 32 * j];

#pragma unroll
    for (int i = 0; i < 16; i++) {
        size_t rowoff = (size_t)(ib * 128 + ty * 16 + i) * BNN;
#pragma unroll
        for (int j = 0; j < 4; j++) {
            acc[i][j] = sqi[i] + sqj[j] - 2.0f * acc[i][j];
            g_dists[rowoff + jb * 128 + tx + 32 * j] = acc[i][j];
        }
    }

    if (jb > ib) {
        __syncthreads();
#pragma unroll
        for (int i = 0; i < 16; i++)
#pragma unroll
            for (int j = 0; j < 4; j++)
                Ts[ty * 16 + i][tx + 32 * j] = acc[i][j];
        __syncthreads();
#pragma unroll
        for (int i = 0; i < 16; i++) {
            int cp = ty * 16 + i;
            size_t rowoff = (size_t)(jb * 128 + cp) * BNN;
#pragma unroll
            for (int j = 0; j < 4; j++) {
                int rp = tx + 32 * j;
                g_dists[rowoff + ib * 128 + rp] = Ts[rp][cp];
            }
        }
    }
}

// ---------------- kC: warp-per-row top-11 with warp-replicated list ----------------
__global__ __launch_bounds__(256) void kC() {
    int row  = blockIdx.x * 8 + (threadIdx.x >> 5);
    int lane = threadIdx.x & 31;

    const float4* Drow = (const float4*)(g_dists + (size_t)row * BNN);

    // replicated top-11 list (identical in every lane)
    unsigned long long L[KSEL];
#pragma unroll
    for (int s = 0; s < KSEL; s++) L[s] = KSENT;
    float worstf = __uint_as_float(0x7f800000u);   // +INF

    float4 v = __ldcs(&Drow[lane]);

#pragma unroll 1
    for (int it = 0; it < 64; it++) {
        float4 cur = v;
        if (it < 63) v = __ldcs(&Drow[(it + 1) * 32 + lane]);

        float f[4] = {cur.x, cur.y, cur.z, cur.w};
#pragma unroll
        for (int q = 0; q < 4; q++) {
            unsigned m = __ballot_sync(0xffffffffu, f[q] <= worstf);
            while (m) {
                int src = __ffs(m) - 1;
                m &= m - 1;
                float fv = __shfl_sync(0xffffffffu, f[q], src);
                unsigned long long key =
                    ((unsigned long long)ordkey(fv) << 32) |
                    (unsigned)(it * 128 + src * 4 + q);
                if (key < L[KSEL - 1]) {
                    L[KSEL - 1] = key;
#pragma unroll
                    for (int p = KSEL - 1; p > 0; --p) {
                        unsigned long long a = L[p - 1], b = L[p];
                        bool sw = b < a;
                        L[p - 1] = sw ? b : a;
                        L[p]     = sw ? a : b;
                    }
                    worstf = invordkey((unsigned)(L[KSEL - 1] >> 32));
                }
            }
        }
    }

    // lists are replicated & sorted ascending: lane m < 11 emits entry m
    if (lane < KSEL) {
        int idx;
#pragma unroll
        for (int p = 0; p < KSEL; p++)
            if (p == lane) idx = (int)(L[p] & 0xffffffffu);
        g_inds[row * KSEL + lane] = idx;
        atomicAdd(&g_de[idx], 1);
    }
}

// ---------------- kScat ----------------
__global__ __launch_bounds__(256) void kScat() {
    __shared__ int si[4 * KSEL];
    int tid = threadIdx.x;
    int node0 = blockIdx.x * 4;
    if (tid < 4 * KSEL) si[tid] = g_inds[node0 * KSEL + tid];
    __syncthreads();
    int n = tid >> 6, c = tid & 63;
    float uv = g_u[(node0 + n) * CC + c];
#pragma unroll
    for (int m = 0; m < KSEL; m++)
        atomicAdd(&g_sknn[si[n * KSEL + m] * CC + c], uv);
}

// ---------------- kLoc ----------------
__global__ __launch_bounds__(64) void kLoc() {
    int e = blockIdx.x;
    int c = threadIdx.x;
    int b  = e / 196, le = e % 196;
    int er = le / 14, ec = le % 14;
    int base = b * NROWS + er * 2 * 32 + ec * 2;
    float s = 0.0f;
#pragma unroll
    for (int dr = 0; dr < 5; dr++)
#pragma unroll
        for (int dc = 0; dc < 5; dc++)
            s += g_u[(base + dr * 32 + dc) * CC + c];
    g_sloc[e * CC + c] = s * (1.0f / 25.0f);
}

// ---------------- kScale ----------------
__global__ void kScale() {
    int i = blockIdx.x * 256 + threadIdx.x;
    int j = i >> 6;
    g_sknn[i] *= (1.0f / (float)g_de[j]);
}

// ---------------- kE: gather z + BN stats ----------------
__global__ __launch_bounds__(256) void kE() {
    __shared__ int si[4 * KSEL];
    __shared__ float red[256], red2[256];
    int tid = threadIdx.x;
    int node0 = blockIdx.x * 4;
    if (tid < 4 * KSEL) si[tid] = g_inds[node0 * KSEL + tid];
    __syncthreads();
    int n = tid >> 6, c = tid & 63;
    int node = node0 + n;

    float acc = 0.0f;
#pragma unroll
    for (int m = 0; m < KSEL; m++)
        acc += g_sknn[si[n * KSEL + m] * CC + c];

    int ln = node & (NROWS - 1);
    int r = ln >> 5, cc2 = ln & 31;
    int b = node >> 10;
    int sr0 = r - 4; if (sr0 < 0) sr0 = 0; sr0 += (sr0 & 1);
    int sr1 = r;     if (sr1 > 26) sr1 = 26; sr1 -= (sr1 & 1);
    int sc0 = cc2 - 4; if (sc0 < 0) sc0 = 0; sc0 += (sc0 & 1);
    int sc1 = cc2;     if (sc1 > 26) sc1 = 26; sc1 -= (sc1 & 1);
    for (int sr = sr0; sr <= sr1; sr += 2)
        for (int sc = sc0; sc <= sc1; sc += 2)
            acc += g_sloc[(b * 196 + (sr >> 1) * 14 + (sc >> 1)) * CC + c];

    float z = acc * dv2f(node);
    g_z[node * CC + c] = z;

    red[tid] = z; red2[tid] = z * z;
    __syncthreads();
    if (tid < 128) { red[tid] += red[tid + 128]; red2[tid] += red2[tid + 128]; }
    __syncthreads();
    if (tid < 64) {
        atomicAdd(&g_stats[tid],      red[tid]  + red[tid + 64]);
        atomicAdd(&g_stats[64 + tid], red2[tid] + red2[tid + 64]);
    }
}

// ---------------- kG ----------------
__global__ void kG(const float* __restrict__ x,
                   const float* __restrict__ gamma,
                   const float* __restrict__ beta,
                   float* __restrict__ out) {
    int i = blockIdx.x * 256 + threadIdx.x;
    int c = i & 63;
    float mu  = g_stats[c]      * (1.0f / (float)BNN);
    float ex2 = g_stats[64 + c] * (1.0f / (float)BNN);
    float var = ex2 - mu * mu;
    float rstd = 1.0f / sqrtf(var + 1e-5f);
    float zn = (g_z[i] - mu) * rstd * gamma[c] + beta[c];
    out[i] = fmaxf(zn, 0.0f) + x[i];
}

// ---------------- launch ----------------
extern "C" void kernel_launch(void* const* d_in, const int* in_sizes, int n_in,
                              void* d_out, int out_size) {
    const float* x     = (const float*)d_in[0];
    const float* W     = (const float*)d_in[1];
    const float* bconv = (const float*)d_in[2];
    const float* gamma = (const float*)d_in[3];
    const float* beta  = (const float*)d_in[4];
    float* out = (float*)d_out;

    const int SMEM_B = 2 * 64 * 129 * sizeof(float);
    cudaFuncSetAttribute(kB, cudaFuncAttributeMaxDynamicSharedMemorySize, SMEM_B);

    kZero <<<2048, 256>>>();
    kA    <<<BNN / 4, 256>>>(x, W, bconv);
    kB    <<<dim3(64, 64), 256, SMEM_B>>>(x);
    kC    <<<BNN / 8, 256>>>();
    kScat <<<BNN / 4, 256>>>();
    kLoc  <<<NLOC, 64>>>();
    kScale<<<2048, 256>>>();
    kE    <<<BNN / 4, 256>>>();
    kG    <<<2048, 256>>>(x, gamma, beta, out);
}

// round 9
// speedup vs baseline: 2.1180x; 1.0561x over previous
#include <cuda_runtime.h>
#include <math.h>

// ---------------- static problem config ----------------
#define BNN    8192
#define CC     64
#define KSEL   11
#define NLOC   1568
#define NROWS  1024

// ---------------- device scratch ----------------
__device__ float g_dists[(size_t)BNN * BNN];
__device__ float g_u[BNN * CC];
__device__ float g_sq[BNN];
__device__ int   g_inds[BNN * KSEL];
__device__ int   g_de[BNN];
__device__ float g_sknn[BNN * CC];
__device__ float g_sloc[NLOC * CC];
__device__ float g_z[BNN * CC];
__device__ float g_stats[2 * CC];
__device__ unsigned g_rowmin[(size_t)BNN * 64];   // per-(row, 128-col-chunk) min as ordkey

// ---------------- helpers ----------------
__device__ __forceinline__ int covdim(int r) {
    int lo = r - 4; if (lo < 0) lo = 0;
    int hi = r;     if (hi > 26) hi = 26;
    if (hi < lo) return 0;
    return hi / 2 - (lo + 1) / 2 + 1;
}

__device__ __forceinline__ float dv2f(int node) {
    int ln = node & (NROWS - 1);
    int r = ln >> 5, c = ln & 31;
    int deg = covdim(r) * covdim(c);
    return 1.0f / sqrtf((float)(KSEL + deg));
}

__device__ __forceinline__ unsigned ordkey(float f) {
    unsigned u = __float_as_uint(f);
    return (u & 0x80000000u) ? ~u : (u | 0x80000000u);
}
__device__ __forceinline__ float invordkey(unsigned k) {
    unsigned u = (k & 0x80000000u) ? (k ^ 0x80000000u) : ~k;
    return __uint_as_float(u);
}

#define KSENT 0xFF800000FFFFFFFFull

// ---------------- kZero ----------------
__global__ void kZero() {
    int i = blockIdx.x * 256 + threadIdx.x;
    if (i < BNN * CC) g_sknn[i] = 0.0f;
    if (i < BNN)      g_de[i]   = 0;
    if (i < 2 * CC)   g_stats[i] = 0.0f;
}

// ---------------- kA: sq norms + u = dv2 * (x W^T + b) ----------------
__global__ __launch_bounds__(256) void kA(const float* __restrict__ x,
                                          const float* __restrict__ W,
                                          const float* __restrict__ bconv) {
    __shared__ float Ws[CC][CC + 1];
    __shared__ float xs[4][CC];
    __shared__ float red[256];
    int tid = threadIdx.x;
    int node0 = blockIdx.x * 4;

    for (int i = tid; i < CC * CC; i += 256) Ws[i >> 6][i & 63] = W[i];
    for (int i = tid; i < 4 * CC; i += 256) xs[i >> 6][i & 63] = x[node0 * CC + i];
    __syncthreads();

    int n = tid >> 6, c = tid & 63;
    int node = node0 + n;

    float v = xs[n][c];
    red[tid] = v * v;
    __syncthreads();
    if (c < 32) red[tid] += red[tid + 32]; __syncthreads();
    if (c < 16) red[tid] += red[tid + 16]; __syncthreads();
    if (c < 8)  red[tid] += red[tid + 8];  __syncthreads();
    if (c < 4)  red[tid] += red[tid + 4];  __syncthreads();
    if (c < 2)  red[tid] += red[tid + 2];  __syncthreads();
    if (c < 1)  red[tid] += red[tid + 1];  __syncthreads();
    if (c == 0) g_sq[node] = red[tid];

    float acc = bconv[c];
#pragma unroll
    for (int k = 0; k < CC; k++) acc += xs[n][k] * Ws[c][k];
    g_u[node * CC + c] = acc * dv2f(node);
}

// ---------------- kB: upper-triangle distance GEMM + mirror + chunk-min epilogue ----------------
__global__ __launch_bounds__(256, 2) void kB(const float* __restrict__ x) {
    extern __shared__ float sm[];
    float (*As)[129] = (float (*)[129])sm;
    float (*Bs)[129] = (float (*)[129])(sm + 64 * 129);
    float (*Ts)[129] = (float (*)[129])sm;
    __shared__ unsigned sm_cm[128];

    int ib = blockIdx.y, jb = blockIdx.x;
    if (jb < ib) return;
    int tid = threadIdx.x;

    if (tid < 128) sm_cm[tid] = 0xFFFFFFFFu;

#pragma unroll
    for (int it = 0; it < 8; it++) {
        int idx = tid + it * 256;
        int r   = idx >> 4;
        int k4  = (idx & 15) * 4;
        float4 va = *(const float4*)(x + (size_t)(ib * 128 + r) * CC + k4);
        As[k4 + 0][r] = va.x; As[k4 + 1][r] = va.y;
        As[k4 + 2][r] = va.z; As[k4 + 3][r] = va.w;
        float4 vb = *(const float4*)(x + (size_t)(jb * 128 + r) * CC + k4);
        Bs[k4 + 0][r] = vb.x; Bs[k4 + 1][r] = vb.y;
        Bs[k4 + 2][r] = vb.z; Bs[k4 + 3][r] = vb.w;
    }
    __syncthreads();

    int tx = tid & 31;
    int ty = tid >> 5;

    float acc[16][4];
#pragma unroll
    for (int i = 0; i < 16; i++)
#pragma unroll
        for (int j = 0; j < 4; j++) acc[i][j] = 0.0f;

#pragma unroll 4
    for (int k = 0; k < 64; k++) {
        float a[16], b[4];
#pragma unroll
        for (int i = 0; i < 16; i++) a[i] = As[k][ty * 16 + i];
#pragma unroll
        for (int j = 0; j < 4; j++)  b[j] = Bs[k][tx + 32 * j];
#pragma unroll
        for (int i = 0; i < 16; i++)
#pragma unroll
            for (int j = 0; j < 4; j++) acc[i][j] += a[i] * b[j];
    }

    float sqi[16], sqj[4];
#pragma unroll
    for (int i = 0; i < 16; i++) sqi[i] = g_sq[ib * 128 + ty * 16 + i];
#pragma unroll
    for (int j = 0; j < 4; j++)  sqj[j] = g_sq[jb * 128 + tx + 32 * j];

#pragma unroll
    for (int i = 0; i < 16; i++) {
        size_t rowoff = (size_t)(ib * 128 + ty * 16 + i) * BNN;
#pragma unroll
        for (int j = 0; j < 4; j++) {
            acc[i][j] = sqi[i] + sqj[j] - 2.0f * acc[i][j];
            g_dists[rowoff + jb * 128 + tx + 32 * j] = acc[i][j];
        }
    }

    // direct chunk-min: warp (fixed ty) owns rows ty*16+i completely
#pragma unroll
    for (int i = 0; i < 16; i++) {
        float m = fminf(fminf(acc[i][0], acc[i][1]), fminf(acc[i][2], acc[i][3]));
#pragma unroll
        for (int off = 16; off; off >>= 1)
            m = fminf(m, __shfl_xor_sync(0xffffffffu, m, off));
        if (tx == 0)
            g_rowmin[((size_t)(ib * 128 + ty * 16 + i)) * 64 + jb] = ordkey(m);
    }

    if (jb > ib) {
        __syncthreads();   // done reading As/Bs; sm_cm init visible
        // col-min partials -> smem atomicMin (ordkey keeps monotone order incl. negatives)
#pragma unroll
        for (int j = 0; j < 4; j++) {
            float cmv = acc[0][j];
#pragma unroll
            for (int i = 1; i < 16; i++) cmv = fminf(cmv, acc[i][j]);
            atomicMin(&sm_cm[tx + 32 * j], ordkey(cmv));
        }
#pragma unroll
        for (int i = 0; i < 16; i++)
#pragma unroll
            for (int j = 0; j < 4; j++)
                Ts[ty * 16 + i][tx + 32 * j] = acc[i][j];
        __syncthreads();
#pragma unroll
        for (int i = 0; i < 16; i++) {
            int cp = ty * 16 + i;
            size_t rowoff = (size_t)(jb * 128 + cp) * BNN;
#pragma unroll
            for (int j = 0; j < 4; j++) {
                int rp = tx + 32 * j;
                g_dists[rowoff + ib * 128 + rp] = Ts[rp][cp];
            }
        }
        if (tid < 128)
            g_rowmin[((size_t)(jb * 128 + tid)) * 64 + ib] = sm_cm[tid];
    }
}

// ---------------- kC: warp-per-row top-11, chunk-min pruned ----------------
__global__ __launch_bounds__(256) void kC() {
    __shared__ unsigned scm[8][64];
    int w    = threadIdx.x >> 5;
    int row  = blockIdx.x * 8 + w;
    int lane = threadIdx.x & 31;

    const float4* Drow = (const float4*)(g_dists + (size_t)row * BNN);

    unsigned c0 = g_rowmin[(size_t)row * 64 + lane];
    unsigned c1 = g_rowmin[(size_t)row * 64 + 32 + lane];
    scm[w][lane]      = c0;
    scm[w][lane + 32] = c1;
    __syncwarp();

    // Tu >= 11th smallest chunkmin (masked-min rounds; dup-collapse only loosens -> safe)
    unsigned Tu = 0xFFFFFFFFu;
    {
        unsigned x0 = c0, x1 = c1;
#pragma unroll 1
        for (int m = 0; m < KSEL; m++) {
            unsigned lm = x0 < x1 ? x0 : x1;
#pragma unroll
            for (int off = 16; off; off >>= 1) {
                unsigned o = __shfl_xor_sync(0xffffffffu, lm, off);
                lm = o < lm ? o : lm;
            }
            Tu = lm;
            if (x0 == lm) x0 = 0xFFFFFFFFu;
            if (x1 == lm) x1 = 0xFFFFFFFFu;
        }
    }

    unsigned long long L[KSEL];
#pragma unroll
    for (int s = 0; s < KSEL; s++) L[s] = KSENT;
    float worstf = __uint_as_float(0x7f800000u);   // +INF

#pragma unroll 1
    for (int c = 0; c < 64; c++) {
        unsigned wk  = (unsigned)(L[KSEL - 1] >> 32);
        unsigned thr = Tu < wk ? Tu : wk;
        if (scm[w][c] > thr) continue;

        float4 cur = __ldcs(&Drow[c * 32 + lane]);
        float f[4] = {cur.x, cur.y, cur.z, cur.w};
#pragma unroll
        for (int q = 0; q < 4; q++) {
            unsigned m = __ballot_sync(0xffffffffu, f[q] <= worstf);
            while (m) {
                int src = __ffs(m) - 1;
                m &= m - 1;
                float fv = __shfl_sync(0xffffffffu, f[q], src);
                unsigned long long key =
                    ((unsigned long long)ordkey(fv) << 32) |
                    (unsigned)(c * 128 + src * 4 + q);
                if (key < L[KSEL - 1]) {
                    L[KSEL - 1] = key;
#pragma unroll
                    for (int p = KSEL - 1; p > 0; --p) {
                        unsigned long long a = L[p - 1], b = L[p];
                        bool sw = b < a;
                        L[p - 1] = sw ? b : a;
                        L[p]     = sw ? a : b;
                    }
                    worstf = invordkey((unsigned)(L[KSEL - 1] >> 32));
                }
            }
        }
    }

    // lists replicated & sorted ascending: lane m < 11 emits entry m
    if (lane < KSEL) {
        int idx;
#pragma unroll
        for (int p = 0; p < KSEL; p++)
            if (p == lane) idx = (int)(L[p] & 0xffffffffu);
        g_inds[row * KSEL + lane] = idx;
        atomicAdd(&g_de[idx], 1);
    }
}

// ---------------- kScat ----------------
__global__ __launch_bounds__(256) void kScat() {
    __shared__ int si[4 * KSEL];
    int tid = threadIdx.x;
    int node0 = blockIdx.x * 4;
    if (tid < 4 * KSEL) si[tid] = g_inds[node0 * KSEL + tid];
    __syncthreads();
    int n = tid >> 6, c = tid & 63;
    float uv = g_u[(node0 + n) * CC + c];
#pragma unroll
    for (int m = 0; m < KSEL; m++)
        atomicAdd(&g_sknn[si[n * KSEL + m] * CC + c], uv);
}

// ---------------- kLoc ----------------
__global__ __launch_bounds__(64) void kLoc() {
    int e = blockIdx.x;
    int c = threadIdx.x;
    int b  = e / 196, le = e % 196;
    int er = le / 14, ec = le % 14;
    int base = b * NROWS + er * 2 * 32 + ec * 2;
    float s = 0.0f;
#pragma unroll
    for (int dr = 0; dr < 5; dr++)
#pragma unroll
        for (int dc = 0; dc < 5; dc++)
            s += g_u[(base + dr * 32 + dc) * CC + c];
    g_sloc[e * CC + c] = s * (1.0f / 25.0f);
}

// ---------------- kScale ----------------
__global__ void kScale() {
    int i = blockIdx.x * 256 + threadIdx.x;
    int j = i >> 6;
    g_sknn[i] *= (1.0f / (float)g_de[j]);
}

// ---------------- kE: gather z + BN stats ----------------
__global__ __launch_bounds__(256) void kE() {
    __shared__ int si[4 * KSEL];
    __shared__ float red[256], red2[256];
    int tid = threadIdx.x;
    int node0 = blockIdx.x * 4;
    if (tid < 4 * KSEL) si[tid] = g_inds[node0 * KSEL + tid];
    __syncthreads();
    int n = tid >> 6, c = tid & 63;
    int node = node0 + n;

    float acc = 0.0f;
#pragma unroll
    for (int m = 0; m < KSEL; m++)
        acc += g_sknn[si[n * KSEL + m] * CC + c];

    int ln = node & (NROWS - 1);
    int r = ln >> 5, cc2 = ln & 31;
    int b = node >> 10;
    int sr0 = r - 4; if (sr0 < 0) sr0 = 0; sr0 += (sr0 & 1);
    int sr1 = r;     if (sr1 > 26) sr1 = 26; sr1 -= (sr1 & 1);
    int sc0 = cc2 - 4; if (sc0 < 0) sc0 = 0; sc0 += (sc0 & 1);
    int sc1 = cc2;     if (sc1 > 26) sc1 = 26; sc1 -= (sc1 & 1);
    for (int sr = sr0; sr <= sr1; sr += 2)
        for (int sc = sc0; sc <= sc1; sc += 2)
            acc += g_sloc[(b * 196 + (sr >> 1) * 14 + (sc >> 1)) * CC + c];

    float z = acc * dv2f(node);
    g_z[node * CC + c] = z;

    red[tid] = z; red2[tid] = z * z;
    __syncthreads();
    if (tid < 128) { red[tid] += red[tid + 128]; red2[tid] += red2[tid + 128]; }
    __syncthreads();
    if (tid < 64) {
        atomicAdd(&g_stats[tid],      red[tid]  + red[tid + 64]);
        atomicAdd(&g_stats[64 + tid], red2[tid] + red2[tid + 64]);
    }
}

// ---------------- kG ----------------
__global__ void kG(const float* __restrict__ x,
                   const float* __restrict__ gamma,
                   const float* __restrict__ beta,
                   float* __restrict__ out) {
    int i = blockIdx.x * 256 + threadIdx.x;
    int c = i & 63;
    float mu  = g_stats[c]      * (1.0f / (float)BNN);
    float ex2 = g_stats[64 + c] * (1.0f / (float)BNN);
    float var = ex2 - mu * mu;
    float rstd = 1.0f / sqrtf(var + 1e-5f);
    float zn = (g_z[i] - mu) * rstd * gamma[c] + beta[c];
    out[i] = fmaxf(zn, 0.0f) + x[i];
}

// ---------------- launch ----------------
extern "C" void kernel_launch(void* const* d_in, const int* in_sizes, int n_in,
                              void* d_out, int out_size) {
    const float* x     = (const float*)d_in[0];
    const float* W     = (const float*)d_in[1];
    const float* bconv = (const float*)d_in[2];
    const float* gamma = (const float*)d_in[3];
    const float* beta  = (const float*)d_in[4];
    float* out = (float*)d_out;

    const int SMEM_B = 2 * 64 * 129 * sizeof(float);
    cudaFuncSetAttribute(kB, cudaFuncAttributeMaxDynamicSharedMemorySize, SMEM_B);

    kZero <<<2048, 256>>>();
    kA    <<<BNN / 4, 256>>>(x, W, bconv);
    kB    <<<dim3(64, 64), 256, SMEM_B>>>(x);
    kC    <<<BNN / 8, 256>>>();
    kScat <<<BNN / 4, 256>>>();
    kLoc  <<<NLOC, 64>>>();
    kScale<<<2048, 256>>>();
    kE    <<<BNN / 4, 256>>>();
    kG    <<<2048, 256>>>(x, gamma, beta, out);
}

// round 10
// speedup vs baseline: 2.3642x; 1.1163x over previous
#include <cuda_runtime.h>
#include <math.h>

// ---------------- static problem config ----------------
#define BNN    8192
#define CC     64
#define KSEL   11
#define NLOC   1568
#define NROWS  1024

// ---------------- device scratch ----------------
__device__ float g_dists[(size_t)BNN * BNN];
__device__ float g_u[BNN * CC];
__device__ float g_sq[BNN];
__device__ int   g_inds[BNN * KSEL];
__device__ int   g_de[BNN];
__device__ float g_sknn[BNN * CC];
__device__ float g_sloc[NLOC * CC];
__device__ float g_z[BNN * CC];
__device__ float g_stats[2 * CC];
__device__ unsigned g_rowmin[(size_t)BNN * 64];   // per-(row, 128-col-chunk) min as ordkey

// ---------------- helpers ----------------
__device__ __forceinline__ int covdim(int r) {
    int lo = r - 4; if (lo < 0) lo = 0;
    int hi = r;     if (hi > 26) hi = 26;
    if (hi < lo) return 0;
    return hi / 2 - (lo + 1) / 2 + 1;
}

__device__ __forceinline__ float dv2f(int node) {
    int ln = node & (NROWS - 1);
    int r = ln >> 5, c = ln & 31;
    int deg = covdim(r) * covdim(c);
    return 1.0f / sqrtf((float)(KSEL + deg));
}

__device__ __forceinline__ unsigned ordkey(float f) {
    unsigned u = __float_as_uint(f);
    return (u & 0x80000000u) ? ~u : (u | 0x80000000u);
}
__device__ __forceinline__ float invordkey(unsigned k) {
    unsigned u = (k & 0x80000000u) ? (k ^ 0x80000000u) : ~k;
    return __uint_as_float(u);
}

#define KSENT 0xFF800000FFFFFFFFull

// packed f32x2 helpers
__device__ __forceinline__ unsigned long long pack2(float lo, float hi) {
    unsigned long long d;
    asm("mov.b64 %0, {%1, %2};" : "=l"(d) : "f"(lo), "f"(hi));
    return d;
}
__device__ __forceinline__ void unpack2(unsigned long long v, float& lo, float& hi) {
    asm("mov.b64 {%0, %1}, %2;" : "=f"(lo), "=f"(hi) : "l"(v));
}
__device__ __forceinline__ void ffma2(unsigned long long& acc,
                                      unsigned long long a, unsigned long long b) {
    asm("fma.rn.f32x2 %0, %1, %2, %3;" : "=l"(acc) : "l"(a), "l"(b), "l"(acc));
}

// ---------------- kZero ----------------
__global__ void kZero() {
    int i = blockIdx.x * 256 + threadIdx.x;
    if (i < BNN * CC) g_sknn[i] = 0.0f;
    if (i < BNN)      g_de[i]   = 0;
    if (i < 2 * CC)   g_stats[i] = 0.0f;
}

// ---------------- kA: sq norms + u = dv2 * (x W^T + b) ----------------
__global__ __launch_bounds__(256) void kA(const float* __restrict__ x,
                                          const float* __restrict__ W,
                                          const float* __restrict__ bconv) {
    __shared__ float Ws[CC][CC + 1];
    __shared__ float xs[4][CC];
    __shared__ float red[256];
    int tid = threadIdx.x;
    int node0 = blockIdx.x * 4;

    for (int i = tid; i < CC * CC; i += 256) Ws[i >> 6][i & 63] = W[i];
    for (int i = tid; i < 4 * CC; i += 256) xs[i >> 6][i & 63] = x[node0 * CC + i];
    __syncthreads();

    int n = tid >> 6, c = tid & 63;
    int node = node0 + n;

    float v = xs[n][c];
    red[tid] = v * v;
    __syncthreads();
    if (c < 32) red[tid] += red[tid + 32]; __syncthreads();
    if (c < 16) red[tid] += red[tid + 16]; __syncthreads();
    if (c < 8)  red[tid] += red[tid + 8];  __syncthreads();
    if (c < 4)  red[tid] += red[tid + 4];  __syncthreads();
    if (c < 2)  red[tid] += red[tid + 2];  __syncthreads();
    if (c < 1)  red[tid] += red[tid + 1];  __syncthreads();
    if (c == 0) g_sq[node] = red[tid];

    float acc = bconv[c];
#pragma unroll
    for (int k = 0; k < CC; k++) acc += xs[n][k] * Ws[c][k];
    g_u[node * CC + c] = acc * dv2f(node);
}

// ---------------- kB: upper-triangle distance GEMM (FFMA2) + mirror + chunk-min ----------------
#define PAD 130   // even padding -> 8B-aligned row-pairs for LDS.64
__global__ __launch_bounds__(256, 2) void kB(const float* __restrict__ x) {
    extern __shared__ float sm[];
    float (*As)[PAD] = (float (*)[PAD])sm;                 // [64][130]
    float (*Bs)[PAD] = (float (*)[PAD])(sm + 64 * PAD);
    float (*Ts)[129] = (float (*)[129])sm;                 // reuse for transpose
    __shared__ unsigned sm_cm[128];

    int ib = blockIdx.y, jb = blockIdx.x;
    if (jb < ib) return;
    int tid = threadIdx.x;

    if (tid < 128) sm_cm[tid] = 0xFFFFFFFFu;

#pragma unroll
    for (int it = 0; it < 8; it++) {
        int idx = tid + it * 256;
        int r   = idx >> 4;
        int k4  = (idx & 15) * 4;
        float4 va = *(const float4*)(x + (size_t)(ib * 128 + r) * CC + k4);
        As[k4 + 0][r] = va.x; As[k4 + 1][r] = va.y;
        As[k4 + 2][r] = va.z; As[k4 + 3][r] = va.w;
        float4 vb = *(const float4*)(x + (size_t)(jb * 128 + r) * CC + k4);
        Bs[k4 + 0][r] = vb.x; Bs[k4 + 1][r] = vb.y;
        Bs[k4 + 2][r] = vb.z; Bs[k4 + 3][r] = vb.w;
    }
    __syncthreads();

    int tx = tid & 31;
    int ty = tid >> 5;

    // acc2[i][j]: packed rows (ty*16+2i, ty*16+2i+1), col tx+32*j
    unsigned long long acc2[8][4];
#pragma unroll
    for (int i = 0; i < 8; i++)
#pragma unroll
        for (int j = 0; j < 4; j++) acc2[i][j] = 0ull;

#pragma unroll 4
    for (int k = 0; k < 64; k++) {
        unsigned long long a2[8];
#pragma unroll
        for (int i = 0; i < 8; i++)
            a2[i] = *(const unsigned long long*)&As[k][ty * 16 + 2 * i];
        unsigned long long b2[4];
#pragma unroll
        for (int j = 0; j < 4; j++) {
            float b = Bs[k][tx + 32 * j];
            b2[j] = pack2(b, b);
        }
#pragma unroll
        for (int i = 0; i < 8; i++)
#pragma unroll
            for (int j = 0; j < 4; j++) ffma2(acc2[i][j], a2[i], b2[j]);
    }

    float sqj[4];
#pragma unroll
    for (int j = 0; j < 4; j++) sqj[j] = g_sq[jb * 128 + tx + 32 * j];

    // finalize + store + row chunk-mins (warp ty owns rows ty*16..ty*16+15 fully)
#pragma unroll
    for (int i = 0; i < 8; i++) {
        int r0 = ty * 16 + 2 * i;
        float sq0 = g_sq[ib * 128 + r0];
        float sq1 = g_sq[ib * 128 + r0 + 1];
        size_t ro0 = (size_t)(ib * 128 + r0) * BNN;
        size_t ro1 = ro0 + BNN;
        float rm0 = __uint_as_float(0x7f800000u);
        float rm1 = rm0;
#pragma unroll
        for (int j = 0; j < 4; j++) {
            float lo, hi;
            unpack2(acc2[i][j], lo, hi);
            lo = sq0 + sqj[j] - 2.0f * lo;
            hi = sq1 + sqj[j] - 2.0f * hi;
            int col = jb * 128 + tx + 32 * j;
            g_dists[ro0 + col] = lo;
            g_dists[ro1 + col] = hi;
            rm0 = fminf(rm0, lo);
            rm1 = fminf(rm1, hi);
            acc2[i][j] = pack2(lo, hi);     // keep finalized distances for mirror
        }
#pragma unroll
        for (int off = 16; off; off >>= 1) {
            rm0 = fminf(rm0, __shfl_xor_sync(0xffffffffu, rm0, off));
            rm1 = fminf(rm1, __shfl_xor_sync(0xffffffffu, rm1, off));
        }
        if (tx == 0) {
            g_rowmin[((size_t)(ib * 128 + r0)) * 64 + jb]     = ordkey(rm0);
            g_rowmin[((size_t)(ib * 128 + r0 + 1)) * 64 + jb] = ordkey(rm1);
        }
    }

    if (jb > ib) {
        __syncthreads();   // done reading As/Bs; sm_cm init visible
        // col-mins + transpose staging
#pragma unroll
        for (int j = 0; j < 4; j++) {
            float cmv = __uint_as_float(0x7f800000u);
#pragma unroll
            for (int i = 0; i < 8; i++) {
                float lo, hi;
                unpack2(acc2[i][j], lo, hi);
                cmv = fminf(cmv, fminf(lo, hi));
                Ts[ty * 16 + 2 * i][tx + 32 * j]     = lo;
                Ts[ty * 16 + 2 * i + 1][tx + 32 * j] = hi;
            }
            atomicMin(&sm_cm[tx + 32 * j], ordkey(cmv));
        }
        __syncthreads();
#pragma unroll
        for (int i = 0; i < 16; i++) {
            int cp = ty * 16 + i;
            size_t rowoff = (size_t)(jb * 128 + cp) * BNN;
#pragma unroll
            for (int j = 0; j < 4; j++) {
                int rp = tx + 32 * j;
                g_dists[rowoff + ib * 128 + rp] = Ts[rp][cp];
            }
        }
        if (tid < 128)
            g_rowmin[((size_t)(jb * 128 + tid)) * 64 + ib] = sm_cm[tid];
    }
}

// ---------------- kC: warp-per-row top-11, pruned chunk list + prefetch ----------------
__global__ __launch_bounds__(256) void kC() {
    __shared__ unsigned scm[8][64];
    int w    = threadIdx.x >> 5;
    int row  = blockIdx.x * 8 + w;
    int lane = threadIdx.x & 31;

    const float4* Drow = (const float4*)(g_dists + (size_t)row * BNN);

    unsigned c0 = g_rowmin[(size_t)row * 64 + lane];
    unsigned c1 = g_rowmin[(size_t)row * 64 + 32 + lane];
    scm[w][lane]      = c0;
    scm[w][lane + 32] = c1;
    __syncwarp();

    // Tu >= 11th smallest chunkmin (masked-min rounds; dup-collapse only loosens -> safe)
    unsigned Tu = 0xFFFFFFFFu;
    {
        unsigned x0 = c0, x1 = c1;
#pragma unroll 1
        for (int m = 0; m < KSEL; m++) {
            unsigned lm = x0 < x1 ? x0 : x1;
#pragma unroll
            for (int off = 16; off; off >>= 1) {
                unsigned o = __shfl_xor_sync(0xffffffffu, lm, off);
                lm = o < lm ? o : lm;
            }
            Tu = lm;
            if (x0 == lm) x0 = 0xFFFFFFFFu;
            if (x1 == lm) x1 = 0xFFFFFFFFu;
        }
    }

    // surviving chunk list (>= 11 chunks; guaranteed superset of true top-11)
    unsigned live0 = __ballot_sync(0xffffffffu, c0 <= Tu);
    unsigned live1 = __ballot_sync(0xffffffffu, c1 <= Tu);
    int n0 = __popc(live0);
    int n  = n0 + __popc(live1);

    unsigned long long L[KSEL];
#pragma unroll
    for (int s = 0; s < KSEL; s++) L[s] = KSENT;
    float worstf = __uint_as_float(0x7f800000u);

    int c_cur = (n0 > 0) ? (int)__fns(live0, 0, 1) : (32 + (int)__fns(live1, 0, 1));
    float4 v = __ldcs(&Drow[c_cur * 32 + lane]);

#pragma unroll 1
    for (int t = 0; t < n; t++) {
        float4 cur = v;
        int c = c_cur;
        if (t + 1 < n) {
            int tn = t + 1;
            c_cur = (tn < n0) ? (int)__fns(live0, 0, tn + 1)
                              : (32 + (int)__fns(live1, 0, tn - n0 + 1));
            v = __ldcs(&Drow[c_cur * 32 + lane]);
        }

        // skip if this chunk can't beat current worst (after first fills)
        unsigned wk = (unsigned)(L[KSEL - 1] >> 32);
        if (scm[w][c] > wk) continue;

        float f[4] = {cur.x, cur.y, cur.z, cur.w};
#pragma unroll
        for (int q = 0; q < 4; q++) {
            unsigned m = __ballot_sync(0xffffffffu, f[q] <= worstf);
            while (m) {
                int src = __ffs(m) - 1;
                m &= m - 1;
                float fv = __shfl_sync(0xffffffffu, f[q], src);
                unsigned long long key =
                    ((unsigned long long)ordkey(fv) << 32) |
                    (unsigned)(c * 128 + src * 4 + q);
                if (key < L[KSEL - 1]) {
                    L[KSEL - 1] = key;
#pragma unroll
                    for (int p = KSEL - 1; p > 0; --p) {
                        unsigned long long a = L[p - 1], b = L[p];
                        bool sw = b < a;
                        L[p - 1] = sw ? b : a;
                        L[p]     = sw ? a : b;
                    }
                    worstf = invordkey((unsigned)(L[KSEL - 1] >> 32));
                }
            }
        }
    }

    if (lane < KSEL) {
        int idx;
#pragma unroll
        for (int p = 0; p < KSEL; p++)
            if (p == lane) idx = (int)(L[p] & 0xffffffffu);
        g_inds[row * KSEL + lane] = idx;
        atomicAdd(&g_de[idx], 1);
    }
}

// ---------------- kScat ----------------
__global__ __launch_bounds__(256) void kScat() {
    __shared__ int si[4 * KSEL];
    int tid = threadIdx.x;
    int node0 = blockIdx.x * 4;
    if (tid < 4 * KSEL) si[tid] = g_inds[node0 * KSEL + tid];
    __syncthreads();
    int n = tid >> 6, c = tid & 63;
    float uv = g_u[(node0 + n) * CC + c];
#pragma unroll
    for (int m = 0; m < KSEL; m++)
        atomicAdd(&g_sknn[si[n * KSEL + m] * CC + c], uv);
}

// ---------------- kLoc ----------------
__global__ __launch_bounds__(64) void kLoc() {
    int e = blockIdx.x;
    int c = threadIdx.x;
    int b  = e / 196, le = e % 196;
    int er = le / 14, ec = le % 14;
    int base = b * NROWS + er * 2 * 32 + ec * 2;
    float s = 0.0f;
#pragma unroll
    for (int dr = 0; dr < 5; dr++)
#pragma unroll
        for (int dc = 0; dc < 5; dc++)
            s += g_u[(base + dr * 32 + dc) * CC + c];
    g_sloc[e * CC + c] = s * (1.0f / 25.0f);
}

// ---------------- kE: gather z (with fused 1/DE) + BN stats ----------------
__global__ __launch_bounds__(256) void kE() {
    __shared__ int si[4 * KSEL];
    __shared__ float sdr[4 * KSEL];
    __shared__ float red[256], red2[256];
    int tid = threadIdx.x;
    int node0 = blockIdx.x * 4;
    if (tid < 4 * KSEL) si[tid] = g_inds[node0 * KSEL + tid];
    __syncthreads();
    if (tid < 4 * KSEL) sdr[tid] = 1.0f / (float)g_de[si[tid]];
    __syncthreads();
    int n = tid >> 6, c = tid & 63;
    int node = node0 + n;

    float acc = 0.0f;
#pragma unroll
    for (int m = 0; m < KSEL; m++)
        acc += g_sknn[si[n * KSEL + m] * CC + c] * sdr[n * KSEL + m];

    int ln = node & (NROWS - 1);
    int r = ln >> 5, cc2 = ln & 31;
    int b = node >> 10;
    int sr0 = r - 4; if (sr0 < 0) sr0 = 0; sr0 += (sr0 & 1);
    int sr1 = r;     if (sr1 > 26) sr1 = 26; sr1 -= (sr1 & 1);
    int sc0 = cc2 - 4; if (sc0 < 0) sc0 = 0; sc0 += (sc0 & 1);
    int sc1 = cc2;     if (sc1 > 26) sc1 = 26; sc1 -= (sc1 & 1);
    for (int sr = sr0; sr <= sr1; sr += 2)
        for (int sc = sc0; sc <= sc1; sc += 2)
            acc += g_sloc[(b * 196 + (sr >> 1) * 14 + (sc >> 1)) * CC + c];

    float z = acc * dv2f(node);
    g_z[node * CC + c] = z;

    red[tid] = z; red2[tid] = z * z;
    __syncthreads();
    if (tid < 128) { red[tid] += red[tid + 128]; red2[tid] += red2[tid + 128]; }
    __syncthreads();
    if (tid < 64) {
        atomicAdd(&g_stats[tid],      red[tid]  + red[tid + 64]);
        atomicAdd(&g_stats[64 + tid], red2[tid] + red2[tid + 64]);
    }
}

// ---------------- kG ----------------
__global__ void kG(const float* __restrict__ x,
                   const float* __restrict__ gamma,
                   const float* __restrict__ beta,
                   float* __restrict__ out) {
    int i = blockIdx.x * 256 + threadIdx.x;
    int c = i & 63;
    float mu  = g_stats[c]      * (1.0f / (float)BNN);
    float ex2 = g_stats[64 + c] * (1.0f / (float)BNN);
    float var = ex2 - mu * mu;
    float rstd = 1.0f / sqrtf(var + 1e-5f);
    float zn = (g_z[i] - mu) * rstd * gamma[c] + beta[c];
    out[i] = fmaxf(zn, 0.0f) + x[i];
}

// ---------------- launch ----------------
extern "C" void kernel_launch(void* const* d_in, const int* in_sizes, int n_in,
                              void* d_out, int out_size) {
    const float* x     = (const float*)d_in[0];
    const float* W     = (const float*)d_in[1];
    const float* bconv = (const float*)d_in[2];
    const float* gamma = (const float*)d_in[3];
    const float* beta  = (const float*)d_in[4];
    float* out = (float*)d_out;

    const int SMEM_B = 2 * 64 * PAD * sizeof(float);   // 66560 B
    cudaFuncSetAttribute(kB, cudaFuncAttributeMaxDynamicSharedMemorySize, SMEM_B);

    kZero <<<2048, 256>>>();
    kA    <<<BNN / 4, 256>>>(x, W, bconv);
    kB    <<<dim3(64, 64), 256, SMEM_B>>>(x);
    kC    <<<BNN / 8, 256>>>();
    kScat <<<BNN / 4, 256>>>();
    kLoc  <<<NLOC, 64>>>();
    kE    <<<BNN / 4, 256>>>();
    kG    <<<2048, 256>>>(x, gamma, beta, out);
}

// round 11
// speedup vs baseline: 2.9584x; 1.2513x over previous
#include <cuda_runtime.h>
#include <math.h>

// ---------------- static problem config ----------------
#define BNN    8192
#define CC     64
#define KSEL   11
#define NLOC   1568
#define NROWS  1024

// ---------------- device scratch ----------------
__device__ float g_dists[(size_t)BNN * BNN];
__device__ float g_u[BNN * CC];
__device__ float g_sq[BNN];
__device__ int   g_inds[BNN * KSEL];
__device__ int   g_de[BNN];
__device__ float g_sknn[BNN * CC];
__device__ float g_sloc[NLOC * CC];
__device__ float g_z[BNN * CC];
__device__ float g_stats[2 * CC];
__device__ unsigned g_rowmin[(size_t)BNN * 64];   // per-(row, 128-col-chunk) min as ordkey

// ---------------- helpers ----------------
__device__ __forceinline__ int covdim(int r) {
    int lo = r - 4; if (lo < 0) lo = 0;
    int hi = r;     if (hi > 26) hi = 26;
    if (hi < lo) return 0;
    return hi / 2 - (lo + 1) / 2 + 1;
}

__device__ __forceinline__ float dv2f(int node) {
    int ln = node & (NROWS - 1);
    int r = ln >> 5, c = ln & 31;
    int deg = covdim(r) * covdim(c);
    return 1.0f / sqrtf((float)(KSEL + deg));
}

__device__ __forceinline__ unsigned ordkey(float f) {
    unsigned u = __float_as_uint(f);
    return (u & 0x80000000u) ? ~u : (u | 0x80000000u);
}
__device__ __forceinline__ float invordkey(unsigned k) {
    unsigned u = (k & 0x80000000u) ? (k ^ 0x80000000u) : ~k;
    return __uint_as_float(u);
}

#define KSENT 0xFF800000FFFFFFFFull

// packed f32x2 helpers
__device__ __forceinline__ unsigned long long pack2(float lo, float hi) {
    unsigned long long d;
    asm("mov.b64 %0, {%1, %2};" : "=l"(d) : "f"(lo), "f"(hi));
    return d;
}
__device__ __forceinline__ void unpack2(unsigned long long v, float& lo, float& hi) {
    asm("mov.b64 {%0, %1}, %2;" : "=f"(lo), "=f"(hi) : "l"(v));
}
__device__ __forceinline__ void ffma2(unsigned long long& acc,
                                      unsigned long long a, unsigned long long b) {
    asm("fma.rn.f32x2 %0, %1, %2, %3;" : "=l"(acc) : "l"(a), "l"(b), "l"(acc));
}

// ---------------- kZero ----------------
__global__ void kZero() {
    int i = blockIdx.x * 256 + threadIdx.x;
    if (i < BNN * CC) g_sknn[i] = 0.0f;
    if (i < BNN)      g_de[i]   = 0;
    if (i < 2 * CC)   g_stats[i] = 0.0f;
}

// ---------------- kA: sq norms + u = dv2 * (x W^T + b) ----------------
__global__ __launch_bounds__(256) void kA(const float* __restrict__ x,
                                          const float* __restrict__ W,
                                          const float* __restrict__ bconv) {
    __shared__ float Ws[CC][CC + 1];
    __shared__ float xs[4][CC];
    __shared__ float red[256];
    int tid = threadIdx.x;
    int node0 = blockIdx.x * 4;

    for (int i = tid; i < CC * CC; i += 256) Ws[i >> 6][i & 63] = W[i];
    for (int i = tid; i < 4 * CC; i += 256) xs[i >> 6][i & 63] = x[node0 * CC + i];
    __syncthreads();

    int n = tid >> 6, c = tid & 63;
    int node = node0 + n;

    float v = xs[n][c];
    red[tid] = v * v;
    __syncthreads();
    if (c < 32) red[tid] += red[tid + 32]; __syncthreads();
    if (c < 16) red[tid] += red[tid + 16]; __syncthreads();
    if (c < 8)  red[tid] += red[tid + 8];  __syncthreads();
    if (c < 4)  red[tid] += red[tid + 4];  __syncthreads();
    if (c < 2)  red[tid] += red[tid + 2];  __syncthreads();
    if (c < 1)  red[tid] += red[tid + 1];  __syncthreads();
    if (c == 0) g_sq[node] = red[tid];

    float acc = bconv[c];
#pragma unroll
    for (int k = 0; k < CC; k++) acc += xs[n][k] * Ws[c][k];
    g_u[node * CC + c] = acc * dv2f(node);
}

// ---------------- kB: upper-triangle distance GEMM (FFMA2) + mirror + chunk-min ----------------
#define PAD 130   // even padding -> 8B-aligned row-pairs for LDS.64
__global__ __launch_bounds__(256, 2) void kB(const float* __restrict__ x) {
    extern __shared__ float sm[];
    float (*As)[PAD] = (float (*)[PAD])sm;                 // [64][130]
    float (*Bs)[PAD] = (float (*)[PAD])(sm + 64 * PAD);
    float (*Ts)[129] = (float (*)[129])sm;                 // reuse for transpose
    __shared__ unsigned sm_cm[128];

    int ib = blockIdx.y, jb = blockIdx.x;
    if (jb < ib) return;
    int tid = threadIdx.x;

    if (tid < 128) sm_cm[tid] = 0xFFFFFFFFu;

#pragma unroll
    for (int it = 0; it < 8; it++) {
        int idx = tid + it * 256;
        int r   = idx >> 4;
        int k4  = (idx & 15) * 4;
        float4 va = *(const float4*)(x + (size_t)(ib * 128 + r) * CC + k4);
        As[k4 + 0][r] = va.x; As[k4 + 1][r] = va.y;
        As[k4 + 2][r] = va.z; As[k4 + 3][r] = va.w;
        float4 vb = *(const float4*)(x + (size_t)(jb * 128 + r) * CC + k4);
        Bs[k4 + 0][r] = vb.x; Bs[k4 + 1][r] = vb.y;
        Bs[k4 + 2][r] = vb.z; Bs[k4 + 3][r] = vb.w;
    }
    __syncthreads();

    int tx = tid & 31;
    int ty = tid >> 5;

    unsigned long long acc2[8][4];
#pragma unroll
    for (int i = 0; i < 8; i++)
#pragma unroll
        for (int j = 0; j < 4; j++) acc2[i][j] = 0ull;

#pragma unroll 4
    for (int k = 0; k < 64; k++) {
        unsigned long long a2[8];
#pragma unroll
        for (int i = 0; i < 8; i++)
            a2[i] = *(const unsigned long long*)&As[k][ty * 16 + 2 * i];
        unsigned long long b2[4];
#pragma unroll
        for (int j = 0; j < 4; j++) {
            float b = Bs[k][tx + 32 * j];
            b2[j] = pack2(b, b);
        }
#pragma unroll
        for (int i = 0; i < 8; i++)
#pragma unroll
            for (int j = 0; j < 4; j++) ffma2(acc2[i][j], a2[i], b2[j]);
    }

    float sqj[4];
#pragma unroll
    for (int j = 0; j < 4; j++) sqj[j] = g_sq[jb * 128 + tx + 32 * j];

#pragma unroll
    for (int i = 0; i < 8; i++) {
        int r0 = ty * 16 + 2 * i;
        float sq0 = g_sq[ib * 128 + r0];
        float sq1 = g_sq[ib * 128 + r0 + 1];
        size_t ro0 = (size_t)(ib * 128 + r0) * BNN;
        size_t ro1 = ro0 + BNN;
        float rm0 = __uint_as_float(0x7f800000u);
        float rm1 = rm0;
#pragma unroll
        for (int j = 0; j < 4; j++) {
            float lo, hi;
            unpack2(acc2[i][j], lo, hi);
            lo = sq0 + sqj[j] - 2.0f * lo;
            hi = sq1 + sqj[j] - 2.0f * hi;
            int col = jb * 128 + tx + 32 * j;
            g_dists[ro0 + col] = lo;
            g_dists[ro1 + col] = hi;
            rm0 = fminf(rm0, lo);
            rm1 = fminf(rm1, hi);
            acc2[i][j] = pack2(lo, hi);
        }
#pragma unroll
        for (int off = 16; off; off >>= 1) {
            rm0 = fminf(rm0, __shfl_xor_sync(0xffffffffu, rm0, off));
            rm1 = fminf(rm1, __shfl_xor_sync(0xffffffffu, rm1, off));
        }
        if (tx == 0) {
            g_rowmin[((size_t)(ib * 128 + r0)) * 64 + jb]     = ordkey(rm0);
            g_rowmin[((size_t)(ib * 128 + r0 + 1)) * 64 + jb] = ordkey(rm1);
        }
    }

    if (jb > ib) {
        __syncthreads();
#pragma unroll
        for (int j = 0; j < 4; j++) {
            float cmv = __uint_as_float(0x7f800000u);
#pragma unroll
            for (int i = 0; i < 8; i++) {
                float lo, hi;
                unpack2(acc2[i][j], lo, hi);
                cmv = fminf(cmv, fminf(lo, hi));
                Ts[ty * 16 + 2 * i][tx + 32 * j]     = lo;
                Ts[ty * 16 + 2 * i + 1][tx + 32 * j] = hi;
            }
            atomicMin(&sm_cm[tx + 32 * j], ordkey(cmv));
        }
        __syncthreads();
#pragma unroll
        for (int i = 0; i < 16; i++) {
            int cp = ty * 16 + i;
            size_t rowoff = (size_t)(jb * 128 + cp) * BNN;
#pragma unroll
            for (int j = 0; j < 4; j++) {
                int rp = tx + 32 * j;
                g_dists[rowoff + ib * 128 + rp] = Ts[rp][cp];
            }
        }
        if (tid < 128)
            g_rowmin[((size_t)(jb * 128 + tid)) * 64 + ib] = sm_cm[tid];
    }
}

// ---------------- kC: warp-per-row top-11, ordered-chunk candidates ----------------
#define PROC_CHUNK(CCH, FV)                                                        \
    do {                                                                           \
        float f_[4] = {(FV).x, (FV).y, (FV).z, (FV).w};                            \
        _Pragma("unroll")                                                          \
        for (int q_ = 0; q_ < 4; q_++) {                                           \
            unsigned mm_ = __ballot_sync(0xffffffffu, f_[q_] <= worstf);           \
            while (mm_) {                                                          \
                int src_ = __ffs(mm_) - 1;                                         \
                mm_ &= mm_ - 1;                                                    \
                float fv_ = __shfl_sync(0xffffffffu, f_[q_], src_);                \
                unsigned long long key_ =                                          \
                    ((unsigned long long)ordkey(fv_) << 32) |                      \
                    (unsigned)((CCH) * 128 + src_ * 4 + q_);                       \
                if (key_ < L[KSEL - 1]) {                                          \
                    L[KSEL - 1] = key_;                                            \
                    _Pragma("unroll")                                              \
                    for (int p_ = KSEL - 1; p_ > 0; --p_) {                        \
                        unsigned long long a_ = L[p_ - 1], b_ = L[p_];             \
                        bool sw_ = b_ < a_;                                        \
                        L[p_ - 1] = sw_ ? b_ : a_;                                 \
                        L[p_]     = sw_ ? a_ : b_;                                 \
                    }                                                              \
                    worstf = fminf(invordkey((unsigned)(L[KSEL - 1] >> 32)), Tuf); \
                }                                                                  \
            }                                                                      \
        }                                                                          \
    } while (0)

__global__ __launch_bounds__(256) void kC() {
    __shared__ unsigned scm[8][64];
    int w    = threadIdx.x >> 5;
    int row  = blockIdx.x * 8 + w;
    int lane = threadIdx.x & 31;

    const float4* Drow = (const float4*)(g_dists + (size_t)row * BNN);

    unsigned c0 = g_rowmin[(size_t)row * 64 + lane];
    unsigned c1 = g_rowmin[(size_t)row * 64 + 32 + lane];
    scm[w][lane]      = c0;
    scm[w][lane + 32] = c1;
    __syncwarp();

    // phase 1: pop the 11 smallest chunkmins (exactly one distinct chunk/round)
    int order[KSEL];
    unsigned Tu = 0xFFFFFFFFu;
    {
        unsigned x0 = c0, x1 = c1;
#pragma unroll
        for (int m = 0; m < KSEL; m++) {
            unsigned lm = x0 < x1 ? x0 : x1;
#pragma unroll
            for (int off = 16; off; off >>= 1) {
                unsigned o = __shfl_xor_sync(0xffffffffu, lm, off);
                lm = o < lm ? o : lm;
            }
            unsigned b0 = __ballot_sync(0xffffffffu, x0 == lm);
            int chunk;
            if (b0) {
                chunk = __ffs(b0) - 1;
                if (lane == chunk) x0 = 0xFFFFFFFFu;
            } else {
                unsigned b1 = __ballot_sync(0xffffffffu, x1 == lm);
                chunk = 32 + __ffs(b1) - 1;
                if (lane == chunk - 32) x1 = 0xFFFFFFFFu;
            }
            order[m] = chunk;
            Tu = lm;
        }
    }
    float Tuf = invordkey(Tu);

    // phase 2: parallel-load the 11 best chunks, process in quality order
    float4 fa[KSEL];
#pragma unroll
    for (int m = 0; m < KSEL; m++)
        fa[m] = __ldcs(&Drow[order[m] * 32 + lane]);

    unsigned long long L[KSEL];
#pragma unroll
    for (int s = 0; s < KSEL; s++) L[s] = KSENT;
    float worstf = Tuf;

#pragma unroll
    for (int m = 0; m < KSEL; m++) {
        unsigned wk = (unsigned)(L[KSEL - 1] >> 32);
        if (scm[w][order[m]] > wk) continue;
        PROC_CHUNK(order[m], fa[m]);
    }

    // phase 3: tie-exactness — rescan unvisited chunks with chunkmin <= worst key
    {
        unsigned long long vis = 0ull;
#pragma unroll
        for (int m = 0; m < KSEL; m++) vis |= 1ull << order[m];
        unsigned wk = (unsigned)(L[KSEL - 1] >> 32);
        bool need0 = (c0 <= wk) && !((vis >> lane) & 1ull);
        bool need1 = (c1 <= wk) && !((vis >> (lane + 32)) & 1ull);
        unsigned nb0 = __ballot_sync(0xffffffffu, need0);
        unsigned nb1 = __ballot_sync(0xffffffffu, need1);
        while (nb0) {
            int c = __ffs(nb0) - 1; nb0 &= nb0 - 1;
            float4 v = __ldcs(&Drow[c * 32 + lane]);
            PROC_CHUNK(c, v);
        }
        while (nb1) {
            int c = 32 + __ffs(nb1) - 1; nb1 &= nb1 - 1;
            float4 v = __ldcs(&Drow[c * 32 + lane]);
            PROC_CHUNK(c, v);
        }
    }

    // lists replicated & sorted ascending: lane m < 11 emits entry m
    if (lane < KSEL) {
        int idx;
#pragma unroll
        for (int p = 0; p < KSEL; p++)
            if (p == lane) idx = (int)(L[p] & 0xffffffffu);
        g_inds[row * KSEL + lane] = idx;
        atomicAdd(&g_de[idx], 1);
    }
}

// ---------------- kScat ----------------
__global__ __launch_bounds__(256) void kScat() {
    __shared__ int si[4 * KSEL];
    int tid = threadIdx.x;
    int node0 = blockIdx.x * 4;
    if (tid < 4 * KSEL) si[tid] = g_inds[node0 * KSEL + tid];
    __syncthreads();
    int n = tid >> 6, c = tid & 63;
    float uv = g_u[(node0 + n) * CC + c];
#pragma unroll
    for (int m = 0; m < KSEL; m++)
        atomicAdd(&g_sknn[si[n * KSEL + m] * CC + c], uv);
}

// ---------------- kLoc ----------------
__global__ __launch_bounds__(64) void kLoc() {
    int e = blockIdx.x;
    int c = threadIdx.x;
    int b  = e / 196, le = e % 196;
    int er = le / 14, ec = le % 14;
    int base = b * NROWS + er * 2 * 32 + ec * 2;
    float s = 0.0f;
#pragma unroll
    for (int dr = 0; dr < 5; dr++)
#pragma unroll
        for (int dc = 0; dc < 5; dc++)
            s += g_u[(base + dr * 32 + dc) * CC + c];
    g_sloc[e * CC + c] = s * (1.0f / 25.0f);
}

// ---------------- kE: gather z (with fused 1/DE) + BN stats ----------------
__global__ __launch_bounds__(256) void kE() {
    __shared__ int si[4 * KSEL];
    __shared__ float sdr[4 * KSEL];
    __shared__ float red[256], red2[256];
    int tid = threadIdx.x;
    int node0 = blockIdx.x * 4;
    if (tid < 4 * KSEL) si[tid] = g_inds[node0 * KSEL + tid];
    __syncthreads();
    if (tid < 4 * KSEL) sdr[tid] = 1.0f / (float)g_de[si[tid]];
    __syncthreads();
    int n = tid >> 6, c = tid & 63;
    int node = node0 + n;

    float acc = 0.0f;
#pragma unroll
    for (int m = 0; m < KSEL; m++)
        acc += g_sknn[si[n * KSEL + m] * CC + c] * sdr[n * KSEL + m];

    int ln = node & (NROWS - 1);
    int r = ln >> 5, cc2 = ln & 31;
    int b = node >> 10;
    int sr0 = r - 4; if (sr0 < 0) sr0 = 0; sr0 += (sr0 & 1);
    int sr1 = r;     if (sr1 > 26) sr1 = 26; sr1 -= (sr1 & 1);
    int sc0 = cc2 - 4; if (sc0 < 0) sc0 = 0; sc0 += (sc0 & 1);
    int sc1 = cc2;     if (sc1 > 26) sc1 = 26; sc1 -= (sc1 & 1);
    for (int sr = sr0; sr <= sr1; sr += 2)
        for (int sc = sc0; sc <= sc1; sc += 2)
            acc += g_sloc[(b * 196 + (sr >> 1) * 14 + (sc >> 1)) * CC + c];

    float z = acc * dv2f(node);
    g_z[node * CC + c] = z;

    red[tid] = z; red2[tid] = z * z;
    __syncthreads();
    if (tid < 128) { red[tid] += red[tid + 128]; red2[tid] += red2[tid + 128]; }
    __syncthreads();
    if (tid < 64) {
        atomicAdd(&g_stats[tid],      red[tid]  + red[tid + 64]);
        atomicAdd(&g_stats[64 + tid], red2[tid] + red2[tid + 64]);
    }
}

// ---------------- kG ----------------
__global__ void kG(const float* __restrict__ x,
                   const float* __restrict__ gamma,
                   const float* __restrict__ beta,
                   float* __restrict__ out) {
    int i = blockIdx.x * 256 + threadIdx.x;
    int c = i & 63;
    float mu  = g_stats[c]      * (1.0f / (float)BNN);
    float ex2 = g_stats[64 + c] * (1.0f / (float)BNN);
    float var = ex2 - mu * mu;
    float rstd = 1.0f / sqrtf(var + 1e-5f);
    float zn = (g_z[i] - mu) * rstd * gamma[c] + beta[c];
    out[i] = fmaxf(zn, 0.0f) + x[i];
}

// ---------------- launch ----------------
extern "C" void kernel_launch(void* const* d_in, const int* in_sizes, int n_in,
                              void* d_out, int out_size) {
    const float* x     = (const float*)d_in[0];
    const float* W     = (const float*)d_in[1];
    const float* bconv = (const float*)d_in[2];
    const float* gamma = (const float*)d_in[3];
    const float* beta  = (const float*)d_in[4];
    float* out = (float*)d_out;

    const int SMEM_B = 2 * 64 * PAD * sizeof(float);   // 66560 B
    cudaFuncSetAttribute(kB, cudaFuncAttributeMaxDynamicSharedMemorySize, SMEM_B);

    kZero <<<2048, 256>>>();
    kA    <<<BNN / 4, 256>>>(x, W, bconv);
    kB    <<<dim3(64, 64), 256, SMEM_B>>>(x);
    kC    <<<BNN / 8, 256>>>();
    kScat <<<BNN / 4, 256>>>();
    kLoc  <<<NLOC, 64>>>();
    kE    <<<BNN / 4, 256>>>();
    kG    <<<2048, 256>>>(x, gamma, beta, out);
}